// round 5
// baseline (speedup 1.0000x reference)
#include <cuda_runtime.h>
#include <cuda_bf16.h>

#define BPTS   16384
#define NE     8
#define CHUNKD 32
#define EPSF   2.220446049250313e-16f
#define WROWS  1728           // padded K rows per expert: 96+4*256+256+96+256
typedef unsigned int u32;

// ---------------- scratch (static device globals) ----------------------------
__device__ int   g_count[NE];
__device__ int   g_list[NE][BPTS];
__device__ float g_gv[BPTS];
// weights in fragment-native layout: [e][t][n(256)][k'(16)] bf16 hi / lo
__device__ unsigned short g_wh[NE * WROWS * 256];
__device__ unsigned short g_wl[NE * WROWS * 256];

// ---------------- tensor-core helpers ----------------------------------------
__device__ __forceinline__ void mma_bf16(float d[4], u32 a0, u32 a1, u32 a2, u32 a3,
                                         u32 b0, u32 b1) {
    asm volatile(
        "mma.sync.aligned.m16n8k16.row.col.f32.bf16.bf16.f32 "
        "{%0,%1,%2,%3}, {%4,%5,%6,%7}, {%8,%9}, {%0,%1,%2,%3};"
        : "+f"(d[0]), "+f"(d[1]), "+f"(d[2]), "+f"(d[3])
        : "r"(a0), "r"(a1), "r"(a2), "r"(a3), "r"(b0), "r"(b1));
}
__device__ __forceinline__ void ldsm4(u32 r[4], u32 addr) {
    asm volatile("ldmatrix.sync.aligned.m8n8.x4.shared.b16 {%0,%1,%2,%3}, [%4];"
                 : "=r"(r[0]), "=r"(r[1]), "=r"(r[2]), "=r"(r[3]) : "r"(addr));
}

// B fragment loads: 8x ld.global.b32 per (t,gg); d[0..3]=hi, d[4..7]=lo
__device__ __forceinline__ void ldb(const unsigned short* __restrict__ bph,
                                    const unsigned short* __restrict__ bpl,
                                    int q, u32 d[8]) {
    const int o = (q >> 2) * 4096 + (q & 3) * 256;
#pragma unroll
    for (int nb = 0; nb < 2; nb++)
#pragma unroll
        for (int r = 0; r < 2; r++) {
            d[nb * 2 + r]     = *(const u32*)(bph + o + nb * 128 + r * 8);
            d[4 + nb * 2 + r] = *(const u32*)(bpl + o + nb * 128 + r * 8);
        }
}

// GEMM: acc[64x256] += A[64xK] @ W[Kx256], A pre-split bf16 hi/lo in smem,
// W hi/lo in global fragment layout. No __syncthreads inside.
__device__ __forceinline__ void gemm_tc2(
    float (&acc)[2][8][4],
    u32 ah_base, u32 al_base, int rowbytes,
    const unsigned short* __restrict__ Wh, const unsigned short* __restrict__ Wl,
    int nt, int lane, int n_off)
{
    const int g = lane >> 2, tt = lane & 3;
    const unsigned short* bph = Wh + (n_off + g) * 16 + 2 * tt;
    const unsigned short* bpl = Wl + (n_off + g) * 16 + 2 * tt;
    u32 bc[8], bn[8];
    ldb(bph, bpl, 0, bc);
    const int Q = nt * 4;
    u32 ah[2][4], al[2][4];
    for (int t = 0; t < nt; t++) {
        ldsm4(ah[0], ah_base + t * 32);
        ldsm4(ah[1], ah_base + 16 * rowbytes + t * 32);
        ldsm4(al[0], al_base + t * 32);
        ldsm4(al[1], al_base + 16 * rowbytes + t * 32);
#pragma unroll
        for (int gg = 0; gg < 4; gg++) {
            const int q = t * 4 + gg;
            if (q + 1 < Q) ldb(bph, bpl, q + 1, bn);
#pragma unroll
            for (int nb = 0; nb < 2; nb++) {
                const int j = gg * 2 + nb;
                const u32 h0 = bc[nb * 2], h1 = bc[nb * 2 + 1];
                const u32 l0 = bc[4 + nb * 2], l1 = bc[4 + nb * 2 + 1];
#pragma unroll
                for (int im = 0; im < 2; im++) {
                    mma_bf16(acc[im][j], ah[im][0], ah[im][1], ah[im][2], ah[im][3], h0, h1);
                    mma_bf16(acc[im][j], al[im][0], al[im][1], al[im][2], al[im][3], h0, h1);
                    mma_bf16(acc[im][j], ah[im][0], ah[im][1], ah[im][2], ah[im][3], l0, l1);
                }
            }
#pragma unroll
            for (int i = 0; i < 8; i++) bc[i] = bn[i];
        }
    }
}

__device__ __forceinline__ void zero_acc_tc(float (&acc)[2][8][4]) {
#pragma unroll
    for (int im = 0; im < 2; im++)
#pragma unroll
        for (int j = 0; j < 8; j++)
#pragma unroll
            for (int q = 0; q < 4; q++) acc[im][j][q] = 0.f;
}

// epilogue: relu(acc+bias) -> split bf16 hi/lo planes (stride 264)
__device__ __forceinline__ void epi_relu(const float (&acc)[2][8][4],
                                         const float* __restrict__ bias,
                                         unsigned short* a_hi, unsigned short* a_lo,
                                         int tid) {
    const int lane = tid & 31, wid = tid >> 5;
    const int m0 = (wid & 1) * 32, n_off = (wid >> 1) * 64;
    const int g = lane >> 2, tt = lane & 3;
#pragma unroll
    for (int im = 0; im < 2; im++)
#pragma unroll
        for (int j = 0; j < 8; j++) {
            const int c = n_off + j * 8 + 2 * tt;
            const float b0 = bias[c], b1 = bias[c + 1];
            const int rlo = m0 + im * 16 + g, rhi = rlo + 8;
            float v0 = fmaxf(acc[im][j][0] + b0, 0.f);
            float v1 = fmaxf(acc[im][j][1] + b1, 0.f);
            float v2 = fmaxf(acc[im][j][2] + b0, 0.f);
            float v3 = fmaxf(acc[im][j][3] + b1, 0.f);
            __nv_bfloat162 h01 = __floats2bfloat162_rn(v0, v1);
            __nv_bfloat162 h23 = __floats2bfloat162_rn(v2, v3);
            float2 hf01 = __bfloat1622float2(h01);
            float2 hf23 = __bfloat1622float2(h23);
            __nv_bfloat162 l01 = __floats2bfloat162_rn(v0 - hf01.x, v1 - hf01.y);
            __nv_bfloat162 l23 = __floats2bfloat162_rn(v2 - hf23.x, v3 - hf23.y);
            *(u32*)(a_hi + rlo * 264 + c) = *(u32*)&h01;
            *(u32*)(a_hi + rhi * 264 + c) = *(u32*)&h23;
            *(u32*)(a_lo + rlo * 264 + c) = *(u32*)&l01;
            *(u32*)(a_lo + rhi * 264 + c) = *(u32*)&l23;
        }
}

// ---------------- kernel 0: reset ---------------------------------------------
__global__ void reset_kernel() {
    if (threadIdx.x < NE) g_count[threadIdx.x] = 0;
}

// ---------------- kernel 0b: split weights to hi/lo, fragment layout ----------
__global__ void convert_weights(
    const float* __restrict__ ew0, const float* __restrict__ ew1,
    const float* __restrict__ ew2, const float* __restrict__ ew3,
    const float* __restrict__ ew4, const float* __restrict__ ew5,
    const float* __restrict__ ew6) {
    int idx = blockIdx.x * 256 + threadIdx.x;          // < NE*WROWS*256
    int e   = idx / (WROWS * 256);
    int rem = idx - e * (WROWS * 256);
    int r = rem >> 8, n = rem & 255;
    float w = 0.f;
    if (r < 96)        { int k = r;            if (k < 95) w = ew0[((size_t)e * 95 + k) * 256 + n]; }
    else if (r < 352)  { int k = r - 96;       w = ew1[((size_t)e * 256 + k) * 256 + n]; }
    else if (r < 608)  { int k = r - 352;      w = ew2[((size_t)e * 256 + k) * 256 + n]; }
    else if (r < 864)  { int k = r - 608;      w = ew3[((size_t)e * 256 + k) * 256 + n]; }
    else if (r < 1120) { int k = r - 864;      w = ew4[((size_t)e * 256 + k) * 256 + n]; }
    else if (r < 1376) { int k = r - 1120;     w = ew5[((size_t)e * 351 + k) * 256 + n]; }
    else if (r < 1472) { int k = 256 + (r - 1376); if (k < 351) w = ew5[((size_t)e * 351 + k) * 256 + n]; }
    else               { int k = r - 1472;     w = ew6[((size_t)e * 256 + k) * 256 + n]; }
    __nv_bfloat16 h = __float2bfloat16_rn(w);
    float hf = __bfloat162float(h);
    __nv_bfloat16 l = __float2bfloat16_rn(w - hf);
    // fragment-native position: [e][t=r>>4][n][k'=r&15]
    size_t pos = (size_t)e * WROWS * 256 + (size_t)(((r >> 4) * 256 + n) * 16 + (r & 15));
    g_wh[pos] = *(unsigned short*)&h;
    g_wl[pos] = *(unsigned short*)&l;
}

// ---------------- kernel 1: gate network + routing (fp32 scalar, exact) -------
typedef unsigned long long uu64;
__device__ __forceinline__ void ffma2(uu64& d, uu64 a, uu64 b) {
    asm("fma.rn.f32x2 %0, %1, %2, %0;" : "+l"(d) : "l"(a), "l"(b));
}
__device__ __forceinline__ uu64 dup2(float v) {
    uu64 r; asm("mov.b64 %0, {%1, %1};" : "=l"(r) : "r"(__float_as_uint(v))); return r;
}
__device__ __forceinline__ float2 unpk(uu64 v) {
    float2 f; asm("mov.b64 {%0, %1}, %2;" : "=f"(f.x), "=f"(f.y) : "l"(v)); return f;
}

__device__ __forceinline__ void load_wtile(const float* __restrict__ W, int t,
                                           int k_real, float* dst, int tid) {
#pragma unroll
    for (int p = 0; p < 4; p++) {
        int f4 = tid + p * 256;
        int row = f4 >> 6;
        int k = t * 16 + row;
        float4 v = make_float4(0.f, 0.f, 0.f, 0.f);
        if (k < k_real) v = *(const float4*)(W + (size_t)k * 256 + (f4 & 63) * 4);
        *(float4*)(dst + f4 * 4) = v;
    }
}

__device__ __forceinline__ void gemm_acc(const float* __restrict__ S, int ldS,
                                         const float* __restrict__ W,
                                         int k_pad, int k_real,
                                         float* w_s, uu64 acc[8][4], int tid) {
    const int tcol = tid & 31, trow = tid >> 5;
    const int ntiles = k_pad >> 4;
    load_wtile(W, 0, k_real, w_s, tid);
    __syncthreads();
    for (int t = 0; t < ntiles; t++) {
        const float* cur = w_s + (t & 1) * 4096;
        if (t + 1 < ntiles)
            load_wtile(W, t + 1, k_real, w_s + ((t + 1) & 1) * 4096, tid);
        const float* Sb = S + t * 16;
#pragma unroll
        for (int kk = 0; kk < 16; kk += 4) {
            float4 a4[8];
#pragma unroll
            for (int i = 0; i < 8; i++)
                a4[i] = *(const float4*)(Sb + (trow * 8 + i) * ldS + kk);
#pragma unroll
            for (int u = 0; u < 4; u++) {
                const uu64* bp = (const uu64*)(cur + (kk + u) * 256 + tcol * 8);
                uu64 b0 = bp[0], b1 = bp[1], b2 = bp[2], b3 = bp[3];
#pragma unroll
                for (int i = 0; i < 8; i++) {
                    float av = (u == 0) ? a4[i].x : (u == 1) ? a4[i].y
                             : (u == 2) ? a4[i].z : a4[i].w;
                    uu64 avv = dup2(av);
                    ffma2(acc[i][0], avv, b0);
                    ffma2(acc[i][1], avv, b1);
                    ffma2(acc[i][2], avv, b2);
                    ffma2(acc[i][3], avv, b3);
                }
            }
        }
        __syncthreads();
    }
}

__device__ __forceinline__ void zero_acc(uu64 acc[8][4]) {
#pragma unroll
    for (int i = 0; i < 8; i++)
#pragma unroll
        for (int j = 0; j < 4; j++) acc[i][j] = 0ull;
}

__device__ __forceinline__ void store_relu(const uu64 acc[8][4],
                                           const float* __restrict__ bias,
                                           float* dst, int tid) {
    const int tcol = tid & 31, trow = tid >> 5;
    float4 bb0 = *(const float4*)(bias + tcol * 8);
    float4 bb1 = *(const float4*)(bias + tcol * 8 + 4);
#pragma unroll
    for (int i = 0; i < 8; i++) {
        float2 p0 = unpk(acc[i][0]), p1 = unpk(acc[i][1]);
        float2 p2 = unpk(acc[i][2]), p3 = unpk(acc[i][3]);
        float4 v0, v1;
        v0.x = fmaxf(p0.x + bb0.x, 0.f); v0.y = fmaxf(p0.y + bb0.y, 0.f);
        v0.z = fmaxf(p1.x + bb0.z, 0.f); v0.w = fmaxf(p1.y + bb0.w, 0.f);
        v1.x = fmaxf(p2.x + bb1.x, 0.f); v1.y = fmaxf(p2.y + bb1.y, 0.f);
        v1.z = fmaxf(p3.x + bb1.z, 0.f); v1.w = fmaxf(p3.y + bb1.w, 0.f);
        *(float4*)(dst + (trow * 8 + i) * 256 + tcol * 8)     = v0;
        *(float4*)(dst + (trow * 8 + i) * 256 + tcol * 8 + 4) = v1;
    }
}

#define GATE_SMEM_F (20480 + 16384 + 8192)

__global__ __launch_bounds__(256, 1) void gate_kernel(
    const float* __restrict__ x,  const float* __restrict__ sl,
    const float* __restrict__ gw1, const float* __restrict__ gb1,
    const float* __restrict__ gw2, const float* __restrict__ gb2,
    const float* __restrict__ lng, const float* __restrict__ lnb,
    const float* __restrict__ gw3, const float* __restrict__ gb3) {
    extern __shared__ float sm[];
    float* gin  = sm;
    float* hbuf = sm + 20480;
    float* wsm  = sm + 20480 + 16384;
    const int tid = threadIdx.x;
    const int row0 = blockIdx.x * 64;
    const int tcol = tid & 31, trow = tid >> 5;

    for (int idx = tid; idx < 64 * 320; idx += 256) {
        int r = idx / 320, c = idx - r * 320;
        int gi = row0 + r;
        float v = 0.f;
        if (c < 63)       v = x[gi * 63 + c];
        else if (c < 319) v = sl[gi * 256 + (c - 63)];
        gin[idx] = v;
    }
    __syncthreads();

    uu64 acc[8][4];
    zero_acc(acc);
    gemm_acc(gin, 320, gw1, 320, 319, wsm, acc, tid);
    store_relu(acc, gb1, hbuf, tid);
    __syncthreads();

    zero_acc(acc);
    gemm_acc(hbuf, 256, gw2, 256, 256, wsm, acc, tid);
#pragma unroll
    for (int p = 0; p < 4; p++) {
#pragma unroll
        for (int i = 0; i < 8; i++) {
            float2 f = unpk(acc[i][p]);
            int c0 = tcol * 8 + p * 2;
            gin[(trow * 8 + i) * 257 + c0]     = f.x + gb2[c0];
            gin[(trow * 8 + i) * 257 + c0 + 1] = f.y + gb2[c0 + 1];
        }
    }
    __syncthreads();

    {
        int r = tid >> 2, sub = tid & 3;
        float* h2r = gin + r * 257;
        float s = 0.f;
#pragma unroll 8
        for (int k = 0; k < 64; k++) s += h2r[sub + 4 * k];
        s += __shfl_xor_sync(0xffffffffu, s, 1);
        s += __shfl_xor_sync(0xffffffffu, s, 2);
        float mu = s * (1.f / 256.f);
        float vv = 0.f;
#pragma unroll 8
        for (int k = 0; k < 64; k++) {
            float d = h2r[sub + 4 * k] - mu;
            vv += d * d;
        }
        vv += __shfl_xor_sync(0xffffffffu, vv, 1);
        vv += __shfl_xor_sync(0xffffffffu, vv, 2);
        float rstd = rsqrtf(vv * (1.f / 256.f) + 1e-5f);
#pragma unroll 8
        for (int k = 0; k < 64; k++) {
            int c = sub + 4 * k;
            float nv = (h2r[c] - mu) * rstd;
            h2r[c] = nv * lng[c] + lnb[c];
        }
    }
    __syncthreads();

    for (int task = tid; task < 512; task += 256) {
        int r = task >> 3, e = task & 7;
        float d = gb3[e];
        const float* h2r = gin + r * 257;
#pragma unroll 8
        for (int k = 0; k < 256; k++) d += h2r[k] * gw3[k * 8 + e];
        hbuf[r * 8 + e] = d;
    }
    __syncthreads();

    if (tid < 64) {
        int gi = row0 + tid;
        const float* lg = hbuf + tid * 8;
        float best = lg[0];
        int bi = 0;
#pragma unroll
        for (int e = 1; e < 8; e++) {
            float v = lg[e];
            if (v > best) { best = v; bi = e; }
        }
        float ssum = 0.f;
#pragma unroll
        for (int e = 0; e < 8; e++) ssum += expf(lg[e] - best);
        g_gv[gi] = 1.f / ssum;
        int pos = atomicAdd(&g_count[bi], 1);
        g_list[bi][pos] = gi;
    }
}

// ---------------- kernel 2: routed expert MLP (TC, no staging barriers) -------
// smem (bf16): a_hi[64][264] | a_lo[64][264] | h_hi[64][104] | h_lo[64][104]
#define EXP_SMEM_B (2 * 64 * 264 * 2 + 2 * 64 * 104 * 2)
#define EXP_TILES  (BPTS / 64 + NE)

__global__ __launch_bounds__(256, 1) void expert_kernel(
    const float* __restrict__ x,  const float* __restrict__ sl,
    const float* __restrict__ eb0, const float* __restrict__ eb1,
    const float* __restrict__ eb2, const float* __restrict__ eb3,
    const float* __restrict__ eb4, const float* __restrict__ eb5,
    const float* __restrict__ eb6,
    const float* __restrict__ ewo, const float* __restrict__ ebo,
    float* __restrict__ out) {
    int t = blockIdx.x;
    int e, base = 0, n = 0;
    for (e = 0; e < NE; e++) {
        n = g_count[e];
        int T = (n + 63) >> 6;
        if (t < base + T) break;
        base += T;
    }
    if (e == NE) return;
    const int start = (t - base) * 64;
    const int nrows = min(64, n - start);

    extern __shared__ unsigned short smu[];
    unsigned short* a_hi = smu;                    // 64*264
    unsigned short* a_lo = smu + 64 * 264;
    unsigned short* h_hi = smu + 2 * 64 * 264;     // 64*104
    unsigned short* h_lo = h_hi + 64 * 104;
    __shared__ int ridx[64];
    const int tid = threadIdx.x;
    const int lane = tid & 31, wid = tid >> 5;
    const int m0 = (wid & 1) * 32, n_off = (wid >> 1) * 64;

    if (tid < 64) ridx[tid] = (tid < nrows) ? g_list[e][start + tid] : -1;
    __syncthreads();

    // gather h0 = concat(x, latent chunk e) split into bf16 hi/lo planes
    for (int idx = tid; idx < 64 * 104; idx += 256) {
        int r = idx / 104, c = idx - r * 104;
        int gi = ridx[r];
        float v = 0.f;
        if (gi >= 0) {
            if (c < 63)      v = x[gi * 63 + c];
            else if (c < 95) v = sl[gi * 256 + e * CHUNKD + (c - 63)];
        }
        __nv_bfloat16 h = __float2bfloat16_rn(v);
        __nv_bfloat16 l = __float2bfloat16_rn(v - __bfloat162float(h));
        h_hi[idx] = *(unsigned short*)&h;
        h_lo[idx] = *(unsigned short*)&l;
    }
    __syncthreads();

    // per-lane ldmatrix base addresses (row = m0 + (lane&15), col-halves by lane>>4)
    const u32 a_hi_b = (u32)__cvta_generic_to_shared(a_hi)
                     + (u32)((m0 + (lane & 15)) * 264 * 2) + (u32)((lane >> 4) * 16);
    const u32 a_lo_b = (u32)__cvta_generic_to_shared(a_lo)
                     + (u32)((m0 + (lane & 15)) * 264 * 2) + (u32)((lane >> 4) * 16);
    const u32 h_hi_b = (u32)__cvta_generic_to_shared(h_hi)
                     + (u32)((m0 + (lane & 15)) * 104 * 2) + (u32)((lane >> 4) * 16);
    const u32 h_lo_b = (u32)__cvta_generic_to_shared(h_lo)
                     + (u32)((m0 + (lane & 15)) * 104 * 2) + (u32)((lane >> 4) * 16);

    const unsigned short* WH = g_wh + (size_t)e * WROWS * 256;
    const unsigned short* WL = g_wl + (size_t)e * WROWS * 256;
    float acc[2][8][4];

    // L0: h0 (K=96) -> 256
    zero_acc_tc(acc);
    gemm_tc2(acc, h_hi_b, h_lo_b, 104 * 2, WH, WL, 6, lane, n_off);
    __syncthreads();
    epi_relu(acc, eb0 + e * 256, a_hi, a_lo, tid);
    __syncthreads();

    // L1..L4: 256 -> 256
    const float* bl4[4] = { eb1, eb2, eb3, eb4 };
#pragma unroll 1
    for (int l = 0; l < 4; l++) {
        zero_acc_tc(acc);
        gemm_tc2(acc, a_hi_b, a_lo_b, 264 * 2,
                 WH + (size_t)(96 + l * 256) * 256, WL + (size_t)(96 + l * 256) * 256,
                 16, lane, n_off);
        __syncthreads();
        epi_relu(acc, bl4[l] + e * 256, a_hi, a_lo, tid);
        __syncthreads();
    }

    // L5 (skip): act part (K=256) + h0 part (K=96)
    zero_acc_tc(acc);
    gemm_tc2(acc, a_hi_b, a_lo_b, 264 * 2,
             WH + (size_t)1120 * 256, WL + (size_t)1120 * 256, 16, lane, n_off);
    gemm_tc2(acc, h_hi_b, h_lo_b, 104 * 2,
             WH + (size_t)1376 * 256, WL + (size_t)1376 * 256, 6, lane, n_off);
    __syncthreads();
    epi_relu(acc, eb5 + e * 256, a_hi, a_lo, tid);
    __syncthreads();

    // L6
    zero_acc_tc(acc);
    gemm_tc2(acc, a_hi_b, a_lo_b, 264 * 2,
             WH + (size_t)1472 * 256, WL + (size_t)1472 * 256, 16, lane, n_off);
    __syncthreads();
    epi_relu(acc, eb6 + e * 256, a_hi, a_lo, tid);
    __syncthreads();

    // output head: y = act @ ewo[e] + ebo[e]; combine with gate
    {
        int r = tid >> 2, o = tid & 3;
        if (r < nrows) {
            float d = ebo[e * 4 + o];
            const float* wo = ewo + (size_t)e * 1024 + o;
            const __nv_bfloat162* ah2 = (const __nv_bfloat162*)(a_hi + r * 264);
            const __nv_bfloat162* al2 = (const __nv_bfloat162*)(a_lo + r * 264);
#pragma unroll 8
            for (int k = 0; k < 128; k++) {
                float2 hv = __bfloat1622float2(ah2[k]);
                float2 lv = __bfloat1622float2(al2[k]);
                d += (hv.x + lv.x) * wo[(2 * k) * 4];
                d += (hv.y + lv.y) * wo[(2 * k + 1) * 4];
            }
            int gi = ridx[r];
            float comb = g_gv[gi] * expf(d);
            if (comb == 0.f) comb = EPSF;
            out[gi * 4 + o] = logf(comb);
        }
    }
}

// ---------------- launch -----------------------------------------------------
extern "C" void kernel_launch(void* const* d_in, const int* in_sizes, int n_in,
                              void* d_out, int out_size) {
    const float* x   = (const float*)d_in[0];
    const float* sl  = (const float*)d_in[1];
    const float* gw1 = (const float*)d_in[2];
    const float* gb1 = (const float*)d_in[3];
    const float* gw2 = (const float*)d_in[4];
    const float* gb2 = (const float*)d_in[5];
    const float* lng = (const float*)d_in[6];
    const float* lnb = (const float*)d_in[7];
    const float* gw3 = (const float*)d_in[8];
    const float* gb3 = (const float*)d_in[9];
    const float* ew0 = (const float*)d_in[10];
    const float* eb0 = (const float*)d_in[11];
    const float* ew1 = (const float*)d_in[12];
    const float* eb1 = (const float*)d_in[13];
    const float* ew2 = (const float*)d_in[14];
    const float* eb2 = (const float*)d_in[15];
    const float* ew3 = (const float*)d_in[16];
    const float* eb3 = (const float*)d_in[17];
    const float* ew4 = (const float*)d_in[18];
    const float* eb4 = (const float*)d_in[19];
    const float* ew5 = (const float*)d_in[20];
    const float* eb5 = (const float*)d_in[21];
    const float* ew6 = (const float*)d_in[22];
    const float* eb6 = (const float*)d_in[23];
    const float* ewo = (const float*)d_in[24];
    const float* ebo = (const float*)d_in[25];
    float* out = (float*)d_out;

    cudaFuncSetAttribute(gate_kernel, cudaFuncAttributeMaxDynamicSharedMemorySize,
                         GATE_SMEM_F * 4);
    cudaFuncSetAttribute(expert_kernel, cudaFuncAttributeMaxDynamicSharedMemorySize,
                         EXP_SMEM_B);

    reset_kernel<<<1, 32>>>();
    convert_weights<<<NE * WROWS, 256>>>(ew0, ew1, ew2, ew3, ew4, ew5, ew6);
    gate_kernel<<<BPTS / 64, 256, GATE_SMEM_F * 4>>>(x, sl, gw1, gb1, gw2, gb2,
                                                     lng, lnb, gw3, gb3);
    expert_kernel<<<EXP_TILES, 256, EXP_SMEM_B>>>(
        x, sl, eb0, eb1, eb2, eb3, eb4, eb5, eb6, ewo, ebo, out);
}

// round 6
// speedup vs baseline: 1.3725x; 1.3725x over previous
#include <cuda_runtime.h>
#include <cuda_bf16.h>

#define BPTS   16384
#define NE     8
#define CHUNKD 32
#define EPSF   2.220446049250313e-16f
#define WROWS  1728           // padded K rows per expert: 96+4*256+256+96+256
typedef unsigned int u32;

// ---------------- scratch (static device globals) ----------------------------
__device__ int   g_count[NE];
__device__ int   g_list[NE][BPTS];
__device__ float g_gv[BPTS];
// weights row-major [e][k(WROWS)][n(256)] bf16 hi / lo
__device__ unsigned short g_wh[NE * WROWS * 256];
__device__ unsigned short g_wl[NE * WROWS * 256];

// ---------------- tensor-core helpers ----------------------------------------
__device__ __forceinline__ void mma_bf16(float d[4], u32 a0, u32 a1, u32 a2, u32 a3,
                                         u32 b0, u32 b1) {
    asm volatile(
        "mma.sync.aligned.m16n8k16.row.col.f32.bf16.bf16.f32 "
        "{%0,%1,%2,%3}, {%4,%5,%6,%7}, {%8,%9}, {%0,%1,%2,%3};"
        : "+f"(d[0]), "+f"(d[1]), "+f"(d[2]), "+f"(d[3])
        : "r"(a0), "r"(a1), "r"(a2), "r"(a3), "r"(b0), "r"(b1));
}
__device__ __forceinline__ void ldsm4(u32 r[4], u32 addr) {
    asm volatile("ldmatrix.sync.aligned.m8n8.x4.shared.b16 {%0,%1,%2,%3}, [%4];"
                 : "=r"(r[0]), "=r"(r[1]), "=r"(r[2]), "=r"(r[3]) : "r"(addr));
}
__device__ __forceinline__ void ldsm4t(u32 r[4], u32 addr) {
    asm volatile("ldmatrix.sync.aligned.m8n8.x4.trans.shared.b16 {%0,%1,%2,%3}, [%4];"
                 : "=r"(r[0]), "=r"(r[1]), "=r"(r[2]), "=r"(r[3]) : "r"(addr));
}
#define CP16(dst, src) \
    asm volatile("cp.async.cg.shared.global [%0], [%1], 16;" :: "r"(dst), "l"(src))
#define CPCOMMIT() asm volatile("cp.async.commit_group;")
#define CPWAIT0()  asm volatile("cp.async.wait_group 0;")

// ---------------- weight chunk staging (32 k-rows, hi+lo) ---------------------
// smem plane: rows stride 264 bf16 (528 B); hi plane then lo plane (+16896 B).
// One buffer = 33792 B. 2048 x 16B copies -> 8 per thread.
__device__ __forceinline__ void stage_chunk32(
    u32 dst_base, const unsigned short* __restrict__ Wh,
    const unsigned short* __restrict__ Wl, int c, int tid) {
#pragma unroll
    for (int p = 0; p < 8; p++) {
        int uu = tid + p * 256;
        int isLo = uu >> 10;
        int v = uu & 1023;
        int row = v >> 5, col = v & 31;
        const unsigned short* src =
            (isLo ? Wl : Wh) + (size_t)(c * 32 + row) * 256 + col * 8;
        u32 dst = dst_base + isLo * 16896 + row * 528 + col * 16;
        CP16(dst, src);
    }
}

// GEMM: acc[64x256] += A[64xK] @ W[Kx256]; A pre-split bf16 hi/lo planes in
// smem (ldmatrix), W staged hi/lo via cp.async double-buffered 32-row chunks.
__device__ __forceinline__ void gemm_tc3(
    float (&acc)[2][8][4],
    u32 a_hi_b, u32 a_lo_b, int rowbytes,
    const unsigned short* __restrict__ Wh, const unsigned short* __restrict__ Wl,
    int nc, u32 wstu, u32 bboff, int tid)
{
    stage_chunk32(wstu, Wh, Wl, 0, tid);
    CPCOMMIT();
    u32 ah[2][4], al[2][4], bh[4], bl[4];
    for (int c = 0; c < nc; c++) {
        CPWAIT0();
        __syncthreads();
        if (c + 1 < nc) {
            stage_chunk32(wstu + ((c + 1) & 1) * 33792, Wh, Wl, c + 1, tid);
            CPCOMMIT();
        }
        const u32 cur = wstu + (c & 1) * 33792;
#pragma unroll
        for (int ks = 0; ks < 2; ks++) {
            const u32 aoff = (u32)(c * 64 + ks * 32);
            ldsm4(ah[0], a_hi_b + aoff);
            ldsm4(ah[1], a_hi_b + 16 * rowbytes + aoff);
            ldsm4(al[0], a_lo_b + aoff);
            ldsm4(al[1], a_lo_b + 16 * rowbytes + aoff);
            const u32 bb = cur + bboff + ks * 8448;
#pragma unroll
            for (int gg = 0; gg < 4; gg++) {
                ldsm4t(bh, bb + gg * 32);
                ldsm4t(bl, bb + 16896 + gg * 32);
#pragma unroll
                for (int nb = 0; nb < 2; nb++) {
                    const int j = gg * 2 + nb;
                    const u32 b0 = bh[2 * nb], b1 = bh[2 * nb + 1];
                    const u32 c0 = bl[2 * nb], c1 = bl[2 * nb + 1];
#pragma unroll
                    for (int im = 0; im < 2; im++) {
                        mma_bf16(acc[im][j], ah[im][0], ah[im][1], ah[im][2], ah[im][3], b0, b1);
                        mma_bf16(acc[im][j], al[im][0], al[im][1], al[im][2], al[im][3], b0, b1);
                        mma_bf16(acc[im][j], ah[im][0], ah[im][1], ah[im][2], ah[im][3], c0, c1);
                    }
                }
            }
        }
    }
}

__device__ __forceinline__ void zero_acc_tc(float (&acc)[2][8][4]) {
#pragma unroll
    for (int im = 0; im < 2; im++)
#pragma unroll
        for (int j = 0; j < 8; j++)
#pragma unroll
            for (int q = 0; q < 4; q++) acc[im][j][q] = 0.f;
}

// epilogue: relu(acc+bias) -> split bf16 hi/lo planes (stride 264)
__device__ __forceinline__ void epi_relu(const float (&acc)[2][8][4],
                                         const float* __restrict__ bias,
                                         unsigned short* a_hi, unsigned short* a_lo,
                                         int tid) {
    const int lane = tid & 31, wid = tid >> 5;
    const int m0 = (wid & 1) * 32, n_off = (wid >> 1) * 64;
    const int g = lane >> 2, tt = lane & 3;
#pragma unroll
    for (int im = 0; im < 2; im++)
#pragma unroll
        for (int j = 0; j < 8; j++) {
            const int c = n_off + j * 8 + 2 * tt;
            const float b0 = bias[c], b1 = bias[c + 1];
            const int rlo = m0 + im * 16 + g, rhi = rlo + 8;
            float v0 = fmaxf(acc[im][j][0] + b0, 0.f);
            float v1 = fmaxf(acc[im][j][1] + b1, 0.f);
            float v2 = fmaxf(acc[im][j][2] + b0, 0.f);
            float v3 = fmaxf(acc[im][j][3] + b1, 0.f);
            __nv_bfloat162 h01 = __floats2bfloat162_rn(v0, v1);
            __nv_bfloat162 h23 = __floats2bfloat162_rn(v2, v3);
            float2 hf01 = __bfloat1622float2(h01);
            float2 hf23 = __bfloat1622float2(h23);
            __nv_bfloat162 l01 = __floats2bfloat162_rn(v0 - hf01.x, v1 - hf01.y);
            __nv_bfloat162 l23 = __floats2bfloat162_rn(v2 - hf23.x, v3 - hf23.y);
            *(u32*)(a_hi + rlo * 264 + c) = *(u32*)&h01;
            *(u32*)(a_hi + rhi * 264 + c) = *(u32*)&h23;
            *(u32*)(a_lo + rlo * 264 + c) = *(u32*)&l01;
            *(u32*)(a_lo + rhi * 264 + c) = *(u32*)&l23;
        }
}

// ---------------- kernel 0: reset ---------------------------------------------
__global__ void reset_kernel() {
    if (threadIdx.x < NE) g_count[threadIdx.x] = 0;
}

// ---------------- kernel 0b: split weights to bf16 hi/lo (row-major) ----------
__global__ void convert_weights(
    const float* __restrict__ ew0, const float* __restrict__ ew1,
    const float* __restrict__ ew2, const float* __restrict__ ew3,
    const float* __restrict__ ew4, const float* __restrict__ ew5,
    const float* __restrict__ ew6) {
    int idx = blockIdx.x * 256 + threadIdx.x;          // < NE*WROWS*256
    int e   = idx / (WROWS * 256);
    int rem = idx - e * (WROWS * 256);
    int r = rem >> 8, n = rem & 255;
    float w = 0.f;
    if (r < 96)        { int k = r;            if (k < 95) w = ew0[((size_t)e * 95 + k) * 256 + n]; }
    else if (r < 352)  { int k = r - 96;       w = ew1[((size_t)e * 256 + k) * 256 + n]; }
    else if (r < 608)  { int k = r - 352;      w = ew2[((size_t)e * 256 + k) * 256 + n]; }
    else if (r < 864)  { int k = r - 608;      w = ew3[((size_t)e * 256 + k) * 256 + n]; }
    else if (r < 1120) { int k = r - 864;      w = ew4[((size_t)e * 256 + k) * 256 + n]; }
    else if (r < 1376) { int k = r - 1120;     w = ew5[((size_t)e * 351 + k) * 256 + n]; }
    else if (r < 1472) { int k = 256 + (r - 1376); if (k < 351) w = ew5[((size_t)e * 351 + k) * 256 + n]; }
    else               { int k = r - 1472;     w = ew6[((size_t)e * 256 + k) * 256 + n]; }
    __nv_bfloat16 h = __float2bfloat16_rn(w);
    float hf = __bfloat162float(h);
    __nv_bfloat16 l = __float2bfloat16_rn(w - hf);
    g_wh[idx] = *(unsigned short*)&h;
    g_wl[idx] = *(unsigned short*)&l;
}

// ---------------- kernel 1: gate network + routing (fp32 scalar, exact) -------
typedef unsigned long long uu64;
__device__ __forceinline__ void ffma2(uu64& d, uu64 a, uu64 b) {
    asm("fma.rn.f32x2 %0, %1, %2, %0;" : "+l"(d) : "l"(a), "l"(b));
}
__device__ __forceinline__ uu64 dup2(float v) {
    uu64 r; asm("mov.b64 %0, {%1, %1};" : "=l"(r) : "r"(__float_as_uint(v))); return r;
}
__device__ __forceinline__ float2 unpk(uu64 v) {
    float2 f; asm("mov.b64 {%0, %1}, %2;" : "=f"(f.x), "=f"(f.y) : "l"(v)); return f;
}

__device__ __forceinline__ void load_wtile(const float* __restrict__ W, int t,
                                           int k_real, float* dst, int tid) {
#pragma unroll
    for (int p = 0; p < 4; p++) {
        int f4 = tid + p * 256;
        int row = f4 >> 6;
        int k = t * 16 + row;
        float4 v = make_float4(0.f, 0.f, 0.f, 0.f);
        if (k < k_real) v = *(const float4*)(W + (size_t)k * 256 + (f4 & 63) * 4);
        *(float4*)(dst + f4 * 4) = v;
    }
}

__device__ __forceinline__ void gemm_acc(const float* __restrict__ S, int ldS,
                                         const float* __restrict__ W,
                                         int k_pad, int k_real,
                                         float* w_s, uu64 acc[8][4], int tid) {
    const int tcol = tid & 31, trow = tid >> 5;
    const int ntiles = k_pad >> 4;
    load_wtile(W, 0, k_real, w_s, tid);
    __syncthreads();
    for (int t = 0; t < ntiles; t++) {
        const float* cur = w_s + (t & 1) * 4096;
        if (t + 1 < ntiles)
            load_wtile(W, t + 1, k_real, w_s + ((t + 1) & 1) * 4096, tid);
        const float* Sb = S + t * 16;
#pragma unroll
        for (int kk = 0; kk < 16; kk += 4) {
            float4 a4[8];
#pragma unroll
            for (int i = 0; i < 8; i++)
                a4[i] = *(const float4*)(Sb + (trow * 8 + i) * ldS + kk);
#pragma unroll
            for (int u = 0; u < 4; u++) {
                const uu64* bp = (const uu64*)(cur + (kk + u) * 256 + tcol * 8);
                uu64 b0 = bp[0], b1 = bp[1], b2 = bp[2], b3 = bp[3];
#pragma unroll
                for (int i = 0; i < 8; i++) {
                    float av = (u == 0) ? a4[i].x : (u == 1) ? a4[i].y
                             : (u == 2) ? a4[i].z : a4[i].w;
                    uu64 avv = dup2(av);
                    ffma2(acc[i][0], avv, b0);
                    ffma2(acc[i][1], avv, b1);
                    ffma2(acc[i][2], avv, b2);
                    ffma2(acc[i][3], avv, b3);
                }
            }
        }
        __syncthreads();
    }
}

__device__ __forceinline__ void zero_acc(uu64 acc[8][4]) {
#pragma unroll
    for (int i = 0; i < 8; i++)
#pragma unroll
        for (int j = 0; j < 4; j++) acc[i][j] = 0ull;
}

__device__ __forceinline__ void store_relu(const uu64 acc[8][4],
                                           const float* __restrict__ bias,
                                           float* dst, int tid) {
    const int tcol = tid & 31, trow = tid >> 5;
    float4 bb0 = *(const float4*)(bias + tcol * 8);
    float4 bb1 = *(const float4*)(bias + tcol * 8 + 4);
#pragma unroll
    for (int i = 0; i < 8; i++) {
        float2 p0 = unpk(acc[i][0]), p1 = unpk(acc[i][1]);
        float2 p2 = unpk(acc[i][2]), p3 = unpk(acc[i][3]);
        float4 v0, v1;
        v0.x = fmaxf(p0.x + bb0.x, 0.f); v0.y = fmaxf(p0.y + bb0.y, 0.f);
        v0.z = fmaxf(p1.x + bb0.z, 0.f); v0.w = fmaxf(p1.y + bb0.w, 0.f);
        v1.x = fmaxf(p2.x + bb1.x, 0.f); v1.y = fmaxf(p2.y + bb1.y, 0.f);
        v1.z = fmaxf(p3.x + bb1.z, 0.f); v1.w = fmaxf(p3.y + bb1.w, 0.f);
        *(float4*)(dst + (trow * 8 + i) * 256 + tcol * 8)     = v0;
        *(float4*)(dst + (trow * 8 + i) * 256 + tcol * 8 + 4) = v1;
    }
}

#define GATE_SMEM_F (20480 + 16384 + 8192)

__global__ __launch_bounds__(256, 1) void gate_kernel(
    const float* __restrict__ x,  const float* __restrict__ sl,
    const float* __restrict__ gw1, const float* __restrict__ gb1,
    const float* __restrict__ gw2, const float* __restrict__ gb2,
    const float* __restrict__ lng, const float* __restrict__ lnb,
    const float* __restrict__ gw3, const float* __restrict__ gb3) {
    extern __shared__ float sm[];
    float* gin  = sm;
    float* hbuf = sm + 20480;
    float* wsm  = sm + 20480 + 16384;
    const int tid = threadIdx.x;
    const int row0 = blockIdx.x * 64;
    const int tcol = tid & 31, trow = tid >> 5;

    for (int idx = tid; idx < 64 * 320; idx += 256) {
        int r = idx / 320, c = idx - r * 320;
        int gi = row0 + r;
        float v = 0.f;
        if (c < 63)       v = x[gi * 63 + c];
        else if (c < 319) v = sl[gi * 256 + (c - 63)];
        gin[idx] = v;
    }
    __syncthreads();

    uu64 acc[8][4];
    zero_acc(acc);
    gemm_acc(gin, 320, gw1, 320, 319, wsm, acc, tid);
    store_relu(acc, gb1, hbuf, tid);
    __syncthreads();

    zero_acc(acc);
    gemm_acc(hbuf, 256, gw2, 256, 256, wsm, acc, tid);
#pragma unroll
    for (int p = 0; p < 4; p++) {
#pragma unroll
        for (int i = 0; i < 8; i++) {
            float2 f = unpk(acc[i][p]);
            int c0 = tcol * 8 + p * 2;
            gin[(trow * 8 + i) * 257 + c0]     = f.x + gb2[c0];
            gin[(trow * 8 + i) * 257 + c0 + 1] = f.y + gb2[c0 + 1];
        }
    }
    __syncthreads();

    {
        int r = tid >> 2, sub = tid & 3;
        float* h2r = gin + r * 257;
        float s = 0.f;
#pragma unroll 8
        for (int k = 0; k < 64; k++) s += h2r[sub + 4 * k];
        s += __shfl_xor_sync(0xffffffffu, s, 1);
        s += __shfl_xor_sync(0xffffffffu, s, 2);
        float mu = s * (1.f / 256.f);
        float vv = 0.f;
#pragma unroll 8
        for (int k = 0; k < 64; k++) {
            float d = h2r[sub + 4 * k] - mu;
            vv += d * d;
        }
        vv += __shfl_xor_sync(0xffffffffu, vv, 1);
        vv += __shfl_xor_sync(0xffffffffu, vv, 2);
        float rstd = rsqrtf(vv * (1.f / 256.f) + 1e-5f);
#pragma unroll 8
        for (int k = 0; k < 64; k++) {
            int c = sub + 4 * k;
            float nv = (h2r[c] - mu) * rstd;
            h2r[c] = nv * lng[c] + lnb[c];
        }
    }
    __syncthreads();

    for (int task = tid; task < 512; task += 256) {
        int r = task >> 3, e = task & 7;
        float d = gb3[e];
        const float* h2r = gin + r * 257;
#pragma unroll 8
        for (int k = 0; k < 256; k++) d += h2r[k] * gw3[k * 8 + e];
        hbuf[r * 8 + e] = d;
    }
    __syncthreads();

    if (tid < 64) {
        int gi = row0 + tid;
        const float* lg = hbuf + tid * 8;
        float best = lg[0];
        int bi = 0;
#pragma unroll
        for (int e = 1; e < 8; e++) {
            float v = lg[e];
            if (v > best) { best = v; bi = e; }
        }
        float ssum = 0.f;
#pragma unroll
        for (int e = 0; e < 8; e++) ssum += expf(lg[e] - best);
        g_gv[gi] = 1.f / ssum;
        int pos = atomicAdd(&g_count[bi], 1);
        g_list[bi][pos] = gi;
    }
}

// ---------------- kernel 2: routed expert MLP (TC, cp.async staged) -----------
// smem elems (u16): a_hi[16896] a_lo[16896] h_hi[6656] h_lo[6656] wst[33792]
#define EXP_SMEM_B ((16896 * 2 + 6656 * 2 + 33792) * 2)
#define EXP_TILES  (BPTS / 64 + NE)

__global__ __launch_bounds__(256, 1) void expert_kernel(
    const float* __restrict__ x,  const float* __restrict__ sl,
    const float* __restrict__ eb0, const float* __restrict__ eb1,
    const float* __restrict__ eb2, const float* __restrict__ eb3,
    const float* __restrict__ eb4, const float* __restrict__ eb5,
    const float* __restrict__ eb6,
    const float* __restrict__ ewo, const float* __restrict__ ebo,
    float* __restrict__ out) {
    int t = blockIdx.x;
    int e, base = 0, n = 0;
    for (e = 0; e < NE; e++) {
        n = g_count[e];
        int T = (n + 63) >> 6;
        if (t < base + T) break;
        base += T;
    }
    if (e == NE) return;
    const int start = (t - base) * 64;
    const int nrows = min(64, n - start);

    extern __shared__ unsigned short smu[];
    unsigned short* a_hi = smu;                    // 64*264
    unsigned short* a_lo = smu + 16896;
    unsigned short* h_hi = smu + 2 * 16896;        // 64*104
    unsigned short* h_lo = h_hi + 6656;
    unsigned short* wst  = smu + 2 * 16896 + 2 * 6656;
    __shared__ int ridx[64];
    const int tid = threadIdx.x;
    const int lane = tid & 31, wid = tid >> 5;
    const int m0 = (wid & 1) * 32, n_off = (wid >> 1) * 64;

    if (tid < 64) ridx[tid] = (tid < nrows) ? g_list[e][start + tid] : -1;
    __syncthreads();

    // gather h0 = concat(x, latent chunk e) split into bf16 hi/lo planes
    for (int idx = tid; idx < 64 * 104; idx += 256) {
        int r = idx / 104, c = idx - r * 104;
        int gi = ridx[r];
        float v = 0.f;
        if (gi >= 0) {
            if (c < 63)      v = x[gi * 63 + c];
            else if (c < 95) v = sl[gi * 256 + e * CHUNKD + (c - 63)];
        }
        __nv_bfloat16 h = __float2bfloat16_rn(v);
        __nv_bfloat16 l = __float2bfloat16_rn(v - __bfloat162float(h));
        h_hi[idx] = *(unsigned short*)&h;
        h_lo[idx] = *(unsigned short*)&l;
    }
    __syncthreads();

    // per-lane ldmatrix base addresses (A) and B offset within staged plane
    const u32 a_hi_b = (u32)__cvta_generic_to_shared(a_hi)
                     + (u32)((m0 + (lane & 15)) * 264 * 2) + (u32)((lane >> 4) * 16);
    const u32 a_lo_b = (u32)__cvta_generic_to_shared(a_lo)
                     + (u32)((m0 + (lane & 15)) * 264 * 2) + (u32)((lane >> 4) * 16);
    const u32 h_hi_b = (u32)__cvta_generic_to_shared(h_hi)
                     + (u32)((m0 + (lane & 15)) * 104 * 2) + (u32)((lane >> 4) * 16);
    const u32 h_lo_b = (u32)__cvta_generic_to_shared(h_lo)
                     + (u32)((m0 + (lane & 15)) * 104 * 2) + (u32)((lane >> 4) * 16);
    const u32 wstu = (u32)__cvta_generic_to_shared(wst);
    const u32 bboff = (u32)(((lane & 15) * 264 + n_off + (lane >> 4) * 8) * 2);

    const unsigned short* WH = g_wh + (size_t)e * WROWS * 256;
    const unsigned short* WL = g_wl + (size_t)e * WROWS * 256;
    float acc[2][8][4];

    // L0: h0 (K=96) -> 256
    zero_acc_tc(acc);
    gemm_tc3(acc, h_hi_b, h_lo_b, 104 * 2, WH, WL, 3, wstu, bboff, tid);
    __syncthreads();
    epi_relu(acc, eb0 + e * 256, a_hi, a_lo, tid);
    __syncthreads();

    // L1..L4: 256 -> 256
    const float* bl4[4] = { eb1, eb2, eb3, eb4 };
#pragma unroll 1
    for (int l = 0; l < 4; l++) {
        zero_acc_tc(acc);
        gemm_tc3(acc, a_hi_b, a_lo_b, 264 * 2,
                 WH + (size_t)(96 + l * 256) * 256, WL + (size_t)(96 + l * 256) * 256,
                 8, wstu, bboff, tid);
        __syncthreads();
        epi_relu(acc, bl4[l] + e * 256, a_hi, a_lo, tid);
        __syncthreads();
    }

    // L5 (skip): act part (K=256) + h0 part (K=96)
    zero_acc_tc(acc);
    gemm_tc3(acc, a_hi_b, a_lo_b, 264 * 2,
             WH + (size_t)1120 * 256, WL + (size_t)1120 * 256, 8, wstu, bboff, tid);
    gemm_tc3(acc, h_hi_b, h_lo_b, 104 * 2,
             WH + (size_t)1376 * 256, WL + (size_t)1376 * 256, 3, wstu, bboff, tid);
    __syncthreads();
    epi_relu(acc, eb5 + e * 256, a_hi, a_lo, tid);
    __syncthreads();

    // L6
    zero_acc_tc(acc);
    gemm_tc3(acc, a_hi_b, a_lo_b, 264 * 2,
             WH + (size_t)1472 * 256, WL + (size_t)1472 * 256, 8, wstu, bboff, tid);
    __syncthreads();
    epi_relu(acc, eb6 + e * 256, a_hi, a_lo, tid);
    __syncthreads();

    // output head: y = act @ ewo[e] + ebo[e]; combine with gate
    {
        int r = tid >> 2, o = tid & 3;
        if (r < nrows) {
            float d = ebo[e * 4 + o];
            const float* wo = ewo + (size_t)e * 1024 + o;
            const __nv_bfloat162* ah2 = (const __nv_bfloat162*)(a_hi + r * 264);
            const __nv_bfloat162* al2 = (const __nv_bfloat162*)(a_lo + r * 264);
#pragma unroll 8
            for (int k = 0; k < 128; k++) {
                float2 hv = __bfloat1622float2(ah2[k]);
                float2 lv = __bfloat1622float2(al2[k]);
                d += (hv.x + lv.x) * wo[(2 * k) * 4];
                d += (hv.y + lv.y) * wo[(2 * k + 1) * 4];
            }
            int gi = ridx[r];
            float comb = g_gv[gi] * expf(d);
            if (comb == 0.f) comb = EPSF;
            out[gi * 4 + o] = logf(comb);
        }
    }
}

// ---------------- launch -----------------------------------------------------
extern "C" void kernel_launch(void* const* d_in, const int* in_sizes, int n_in,
                              void* d_out, int out_size) {
    const float* x   = (const float*)d_in[0];
    const float* sl  = (const float*)d_in[1];
    const float* gw1 = (const float*)d_in[2];
    const float* gb1 = (const float*)d_in[3];
    const float* gw2 = (const float*)d_in[4];
    const float* gb2 = (const float*)d_in[5];
    const float* lng = (const float*)d_in[6];
    const float* lnb = (const float*)d_in[7];
    const float* gw3 = (const float*)d_in[8];
    const float* gb3 = (const float*)d_in[9];
    const float* ew0 = (const float*)d_in[10];
    const float* eb0 = (const float*)d_in[11];
    const float* ew1 = (const float*)d_in[12];
    const float* eb1 = (const float*)d_in[13];
    const float* ew2 = (const float*)d_in[14];
    const float* eb2 = (const float*)d_in[15];
    const float* ew3 = (const float*)d_in[16];
    const float* eb3 = (const float*)d_in[17];
    const float* ew4 = (const float*)d_in[18];
    const float* eb4 = (const float*)d_in[19];
    const float* ew5 = (const float*)d_in[20];
    const float* eb5 = (const float*)d_in[21];
    const float* ew6 = (const float*)d_in[22];
    const float* eb6 = (const float*)d_in[23];
    const float* ewo = (const float*)d_in[24];
    const float* ebo = (const float*)d_in[25];
    float* out = (float*)d_out;

    cudaFuncSetAttribute(gate_kernel, cudaFuncAttributeMaxDynamicSharedMemorySize,
                         GATE_SMEM_F * 4);
    cudaFuncSetAttribute(expert_kernel, cudaFuncAttributeMaxDynamicSharedMemorySize,
                         EXP_SMEM_B);

    reset_kernel<<<1, 32>>>();
    convert_weights<<<NE * WROWS, 256>>>(ew0, ew1, ew2, ew3, ew4, ew5, ew6);
    gate_kernel<<<BPTS / 64, 256, GATE_SMEM_F * 4>>>(x, sl, gw1, gb1, gw2, gb2,
                                                     lng, lnb, gw3, gb3);
    expert_kernel<<<EXP_TILES, 256, EXP_SMEM_B>>>(
        x, sl, eb0, eb1, eb2, eb3, eb4, eb5, eb6, ewo, ebo, out);
}

// round 7
// speedup vs baseline: 1.7416x; 1.2689x over previous
#include <cuda_runtime.h>
#include <cuda_fp16.h>

#define BPTS   16384
#define NE     8
#define CHUNKD 32
#define EPSF   2.220446049250313e-16f
#define WROWS  1728           // padded expert K rows: 96+4*256+256+96+256
#define GWROWS 576            // gate: 320 (gw1 padded) + 256 (gw2)
typedef unsigned int u32;
typedef unsigned short u16;

// ---------------- scratch (static device globals) ----------------------------
__device__ int   g_count[NE];
__device__ int   g_list[NE][BPTS];
__device__ float g_gv[BPTS];
// expert weights row-major [e][k][n(256)] fp16 hi / lo
__device__ u16 g_wh[NE * WROWS * 256];
__device__ u16 g_wl[NE * WROWS * 256];
// gate weights [k(576)][n(256)] fp16 hi / lo
__device__ u16 g_gh[GWROWS * 256];
__device__ u16 g_gl[GWROWS * 256];

// ---------------- tensor-core helpers ----------------------------------------
__device__ __forceinline__ void mma_f16(float d[4], u32 a0, u32 a1, u32 a2, u32 a3,
                                        u32 b0, u32 b1) {
    asm volatile(
        "mma.sync.aligned.m16n8k16.row.col.f32.f16.f16.f32 "
        "{%0,%1,%2,%3}, {%4,%5,%6,%7}, {%8,%9}, {%0,%1,%2,%3};"
        : "+f"(d[0]), "+f"(d[1]), "+f"(d[2]), "+f"(d[3])
        : "r"(a0), "r"(a1), "r"(a2), "r"(a3), "r"(b0), "r"(b1));
}
__device__ __forceinline__ void ldsm4(u32 r[4], u32 addr) {
    asm volatile("ldmatrix.sync.aligned.m8n8.x4.shared.b16 {%0,%1,%2,%3}, [%4];"
                 : "=r"(r[0]), "=r"(r[1]), "=r"(r[2]), "=r"(r[3]) : "r"(addr));
}
__device__ __forceinline__ void ldsm4t(u32 r[4], u32 addr) {
    asm volatile("ldmatrix.sync.aligned.m8n8.x4.trans.shared.b16 {%0,%1,%2,%3}, [%4];"
                 : "=r"(r[0]), "=r"(r[1]), "=r"(r[2]), "=r"(r[3]) : "r"(addr));
}
#define CP16(dst, src) \
    asm volatile("cp.async.cg.shared.global [%0], [%1], 16;" :: "r"(dst), "l"(src))
#define CPCOMMIT() asm volatile("cp.async.commit_group;")
#define CPWAIT0()  asm volatile("cp.async.wait_group 0;")

__device__ __forceinline__ void split2h(float v, u16& h, u16& l) {
    __half hh = __float2half_rn(v);
    __half ll = __float2half_rn(v - __half2float(hh));
    h = *(u16*)&hh;  l = *(u16*)&ll;
}

// ---------------- weight chunk staging (32 k-rows, hi+lo) ---------------------
// smem plane rows stride 264 u16 (528 B); hi plane then lo plane (+16896 B).
// One buffer = 33792 B.
__device__ __forceinline__ void stage_chunk32(
    u32 dst_base, const u16* __restrict__ Wh, const u16* __restrict__ Wl,
    int c, int tid) {
#pragma unroll
    for (int p = 0; p < 8; p++) {
        int uu = tid + p * 256;
        int isLo = uu >> 10;
        int v = uu & 1023;
        int row = v >> 5, col = v & 31;
        const u16* src = (isLo ? Wl : Wh) + (size_t)(c * 32 + row) * 256 + col * 8;
        u32 dst = dst_base + isLo * 16896 + row * 528 + col * 16;
        CP16(dst, src);
    }
}

// GEMM: acc[64x256] += A[64xK] @ W[Kx256]; A pre-split fp16 hi/lo planes in
// smem (ldmatrix), W staged hi/lo via cp.async double-buffered 32-row chunks.
__device__ __forceinline__ void gemm_tc3(
    float (&acc)[2][8][4],
    u32 a_hi_b, u32 a_lo_b, int rowbytes,
    const u16* __restrict__ Wh, const u16* __restrict__ Wl,
    int nc, u32 wstu, u32 bboff, int tid)
{
    stage_chunk32(wstu, Wh, Wl, 0, tid);
    CPCOMMIT();
    u32 ah[2][4], al[2][4], bh[4], bl[4];
    for (int c = 0; c < nc; c++) {
        CPWAIT0();
        __syncthreads();
        if (c + 1 < nc) {
            stage_chunk32(wstu + ((c + 1) & 1) * 33792, Wh, Wl, c + 1, tid);
            CPCOMMIT();
        }
        const u32 cur = wstu + (c & 1) * 33792;
#pragma unroll
        for (int ks = 0; ks < 2; ks++) {
            const u32 aoff = (u32)(c * 64 + ks * 32);
            ldsm4(ah[0], a_hi_b + aoff);
            ldsm4(ah[1], a_hi_b + 16 * rowbytes + aoff);
            ldsm4(al[0], a_lo_b + aoff);
            ldsm4(al[1], a_lo_b + 16 * rowbytes + aoff);
            const u32 bb = cur + bboff + ks * 8448;
#pragma unroll
            for (int gg = 0; gg < 4; gg++) {
                ldsm4t(bh, bb + gg * 32);
                ldsm4t(bl, bb + 16896 + gg * 32);
#pragma unroll
                for (int nb = 0; nb < 2; nb++) {
                    const int j = gg * 2 + nb;
                    const u32 b0 = bh[2 * nb], b1 = bh[2 * nb + 1];
                    const u32 c0 = bl[2 * nb], c1 = bl[2 * nb + 1];
#pragma unroll
                    for (int im = 0; im < 2; im++) {
                        mma_f16(acc[im][j], ah[im][0], ah[im][1], ah[im][2], ah[im][3], b0, b1);
                        mma_f16(acc[im][j], al[im][0], al[im][1], al[im][2], al[im][3], b0, b1);
                        mma_f16(acc[im][j], ah[im][0], ah[im][1], ah[im][2], ah[im][3], c0, c1);
                    }
                }
            }
        }
    }
}

__device__ __forceinline__ void zero_acc_tc(float (&acc)[2][8][4]) {
#pragma unroll
    for (int im = 0; im < 2; im++)
#pragma unroll
        for (int j = 0; j < 8; j++)
#pragma unroll
            for (int q = 0; q < 4; q++) acc[im][j][q] = 0.f;
}

// epilogue: relu(acc+bias) -> split fp16 hi/lo planes (stride 264)
__device__ __forceinline__ void epi_relu(const float (&acc)[2][8][4],
                                         const float* __restrict__ bias,
                                         u16* a_hi, u16* a_lo, int tid) {
    const int lane = tid & 31, wid = tid >> 5;
    const int m0 = (wid & 1) * 32, n_off = (wid >> 1) * 64;
    const int g = lane >> 2, tt = lane & 3;
#pragma unroll
    for (int im = 0; im < 2; im++)
#pragma unroll
        for (int j = 0; j < 8; j++) {
            const int c = n_off + j * 8 + 2 * tt;
            const float b0 = bias[c], b1 = bias[c + 1];
            const int rlo = m0 + im * 16 + g, rhi = rlo + 8;
            float v0 = fmaxf(acc[im][j][0] + b0, 0.f);
            float v1 = fmaxf(acc[im][j][1] + b1, 0.f);
            float v2 = fmaxf(acc[im][j][2] + b0, 0.f);
            float v3 = fmaxf(acc[im][j][3] + b1, 0.f);
            __half2 h01 = __floats2half2_rn(v0, v1);
            __half2 h23 = __floats2half2_rn(v2, v3);
            float2 hf01 = __half22float2(h01);
            float2 hf23 = __half22float2(h23);
            __half2 l01 = __floats2half2_rn(v0 - hf01.x, v1 - hf01.y);
            __half2 l23 = __floats2half2_rn(v2 - hf23.x, v3 - hf23.y);
            *(u32*)(a_hi + rlo * 264 + c) = *(u32*)&h01;
            *(u32*)(a_hi + rhi * 264 + c) = *(u32*)&h23;
            *(u32*)(a_lo + rlo * 264 + c) = *(u32*)&l01;
            *(u32*)(a_lo + rhi * 264 + c) = *(u32*)&l23;
        }
}

// gate GEMM2 epilogue: h2 = acc + bias (fp32, stride 257, no relu)
__device__ __forceinline__ void epi_h2(const float (&acc)[2][8][4],
                                       const float* __restrict__ bias,
                                       float* h2, int tid) {
    const int lane = tid & 31, wid = tid >> 5;
    const int m0 = (wid & 1) * 32, n_off = (wid >> 1) * 64;
    const int g = lane >> 2, tt = lane & 3;
#pragma unroll
    for (int im = 0; im < 2; im++)
#pragma unroll
        for (int j = 0; j < 8; j++) {
            const int c = n_off + j * 8 + 2 * tt;
            const float b0 = bias[c], b1 = bias[c + 1];
            const int rlo = m0 + im * 16 + g, rhi = rlo + 8;
            h2[rlo * 257 + c]     = acc[im][j][0] + b0;
            h2[rlo * 257 + c + 1] = acc[im][j][1] + b1;
            h2[rhi * 257 + c]     = acc[im][j][2] + b0;
            h2[rhi * 257 + c + 1] = acc[im][j][3] + b1;
        }
}

// ---------------- kernel 0: reset ---------------------------------------------
__global__ void reset_kernel() {
    if (threadIdx.x < NE) g_count[threadIdx.x] = 0;
}

// ---------------- kernel 0b: split expert weights to fp16 hi/lo ----------------
__global__ void convert_weights(
    const float* __restrict__ ew0, const float* __restrict__ ew1,
    const float* __restrict__ ew2, const float* __restrict__ ew3,
    const float* __restrict__ ew4, const float* __restrict__ ew5,
    const float* __restrict__ ew6) {
    int idx = blockIdx.x * 256 + threadIdx.x;          // < NE*WROWS*256
    int e   = idx / (WROWS * 256);
    int rem = idx - e * (WROWS * 256);
    int r = rem >> 8, n = rem & 255;
    float w = 0.f;
    if (r < 96)        { int k = r;            if (k < 95) w = ew0[((size_t)e * 95 + k) * 256 + n]; }
    else if (r < 352)  { int k = r - 96;       w = ew1[((size_t)e * 256 + k) * 256 + n]; }
    else if (r < 608)  { int k = r - 352;      w = ew2[((size_t)e * 256 + k) * 256 + n]; }
    else if (r < 864)  { int k = r - 608;      w = ew3[((size_t)e * 256 + k) * 256 + n]; }
    else if (r < 1120) { int k = r - 864;      w = ew4[((size_t)e * 256 + k) * 256 + n]; }
    else if (r < 1376) { int k = r - 1120;     w = ew5[((size_t)e * 351 + k) * 256 + n]; }
    else if (r < 1472) { int k = 256 + (r - 1376); if (k < 351) w = ew5[((size_t)e * 351 + k) * 256 + n]; }
    else               { int k = r - 1472;     w = ew6[((size_t)e * 256 + k) * 256 + n]; }
    split2h(w, g_wh[idx], g_wl[idx]);
}

// ---------------- kernel 0c: split gate weights --------------------------------
__global__ void convert_gate_weights(const float* __restrict__ gw1,
                                     const float* __restrict__ gw2) {
    int idx = blockIdx.x * 256 + threadIdx.x;          // < GWROWS*256
    int r = idx >> 8, n = idx & 255;
    float w = 0.f;
    if (r < 320) { if (r < 319) w = gw1[(size_t)r * 256 + n]; }
    else         w = gw2[(size_t)(r - 320) * 256 + n];
    split2h(w, g_gh[idx], g_gl[idx]);
}

// ---------------- kernel 1: gate network + routing (TC fp16-split) -------------
// smem bytes: region0 [0, 84992): gi planes (2 x 64x328 u16) -> h1 planes
//             (2 x 64x264 u16) -> h2 fp32 (64x257) + logits (at 66048)
//             wst at 84992: 2 x 33792 B
#define GATE_SMEM_B (84992 + 67584)

__global__ __launch_bounds__(256, 1) void gate_kernel(
    const float* __restrict__ x,  const float* __restrict__ sl,
    const float* __restrict__ gb1, const float* __restrict__ gb2,
    const float* __restrict__ lng, const float* __restrict__ lnb,
    const float* __restrict__ gw3, const float* __restrict__ gb3) {
    extern __shared__ u16 smu[];
    u16* gi_hi = smu;                       // 64*328
    u16* gi_lo = smu + 20992;
    u16* a_hi  = smu;                       // 64*264 (after GEMM1)
    u16* a_lo  = smu + 16896;
    float* h2    = (float*)smu;             // 64*257 (after GEMM2)
    float* lgbuf = (float*)((char*)smu + 66048);   // 64*8
    const u32 wstu = (u32)__cvta_generic_to_shared((char*)smu + 84992);

    const int tid = threadIdx.x;
    const int row0 = blockIdx.x * 64;
    const int lane = tid & 31, wid = tid >> 5;
    const int m0 = (wid & 1) * 32, n_off = (wid >> 1) * 64;
    const u32 bboff = (u32)(((lane & 15) * 264 + n_off + (lane >> 4) * 8) * 2);

    // gather g_in = concat(x, shape_latent) split into fp16 hi/lo (stride 328)
    for (int idx = tid; idx < 64 * 328; idx += 256) {
        int r = idx / 328, c = idx - r * 328;
        int gi = row0 + r;
        float v = 0.f;
        if (c < 63)       v = x[gi * 63 + c];
        else if (c < 319) v = sl[gi * 256 + (c - 63)];
        split2h(v, gi_hi[idx], gi_lo[idx]);
    }
    __syncthreads();

    const u32 gihi_b = (u32)__cvta_generic_to_shared(gi_hi)
                     + (u32)((m0 + (lane & 15)) * 656) + (u32)((lane >> 4) * 16);
    const u32 gilo_b = (u32)__cvta_generic_to_shared(gi_lo)
                     + (u32)((m0 + (lane & 15)) * 656) + (u32)((lane >> 4) * 16);
    const u32 ahi_b = (u32)__cvta_generic_to_shared(a_hi)
                    + (u32)((m0 + (lane & 15)) * 528) + (u32)((lane >> 4) * 16);
    const u32 alo_b = (u32)__cvta_generic_to_shared(a_lo)
                    + (u32)((m0 + (lane & 15)) * 528) + (u32)((lane >> 4) * 16);

    float acc[2][8][4];

    // GEMM1: g_in (K=320) @ gw1 -> relu -> h1 split planes
    zero_acc_tc(acc);
    gemm_tc3(acc, gihi_b, gilo_b, 656, g_gh, g_gl, 10, wstu, bboff, tid);
    __syncthreads();
    epi_relu(acc, gb1, a_hi, a_lo, tid);
    __syncthreads();

    // GEMM2: h1 (K=256) @ gw2 -> h2 fp32
    zero_acc_tc(acc);
    gemm_tc3(acc, ahi_b, alo_b, 528, g_gh + 320 * 256, g_gl + 320 * 256,
             8, wstu, bboff, tid);
    __syncthreads();
    epi_h2(acc, gb2, h2, tid);
    __syncthreads();

    // LayerNorm per row: 4 threads/row, two-pass
    {
        int r = tid >> 2, sub = tid & 3;
        float* h2r = h2 + r * 257;
        float s = 0.f;
#pragma unroll 8
        for (int k = 0; k < 64; k++) s += h2r[sub + 4 * k];
        s += __shfl_xor_sync(0xffffffffu, s, 1);
        s += __shfl_xor_sync(0xffffffffu, s, 2);
        float mu = s * (1.f / 256.f);
        float vv = 0.f;
#pragma unroll 8
        for (int k = 0; k < 64; k++) {
            float d = h2r[sub + 4 * k] - mu;
            vv += d * d;
        }
        vv += __shfl_xor_sync(0xffffffffu, vv, 1);
        vv += __shfl_xor_sync(0xffffffffu, vv, 2);
        float rstd = rsqrtf(vv * (1.f / 256.f) + 1e-5f);
#pragma unroll 8
        for (int k = 0; k < 64; k++) {
            int c = sub + 4 * k;
            float nv = (h2r[c] - mu) * rstd;
            h2r[c] = nv * lng[c] + lnb[c];
        }
    }
    __syncthreads();

    // logits = h2 @ gw3 + gb3 (fp32 scalar; tiny)
    for (int task = tid; task < 512; task += 256) {
        int r = task >> 3, e = task & 7;
        float d = gb3[e];
        const float* h2r = h2 + r * 257;
#pragma unroll 8
        for (int k = 0; k < 256; k++) d += h2r[k] * gw3[k * 8 + e];
        lgbuf[r * 8 + e] = d;
    }
    __syncthreads();

    // softmax / argmax / append to expert list
    if (tid < 64) {
        int gi = row0 + tid;
        const float* lg = lgbuf + tid * 8;
        float best = lg[0];
        int bi = 0;
#pragma unroll
        for (int e = 1; e < 8; e++) {
            float v = lg[e];
            if (v > best) { best = v; bi = e; }
        }
        float ssum = 0.f;
#pragma unroll
        for (int e = 0; e < 8; e++) ssum += expf(lg[e] - best);
        g_gv[gi] = 1.f / ssum;
        int pos = atomicAdd(&g_count[bi], 1);
        g_list[bi][pos] = gi;
    }
}

// ---------------- kernel 2: routed expert MLP (TC, cp.async staged) -----------
// smem elems (u16): a_hi[16896] a_lo[16896] h_hi[6656] h_lo[6656] wst[33792]
#define EXP_SMEM_B ((16896 * 2 + 6656 * 2 + 33792) * 2)
#define EXP_TILES  (BPTS / 64 + NE)

__global__ __launch_bounds__(256, 1) void expert_kernel(
    const float* __restrict__ x,  const float* __restrict__ sl,
    const float* __restrict__ eb0, const float* __restrict__ eb1,
    const float* __restrict__ eb2, const float* __restrict__ eb3,
    const float* __restrict__ eb4, const float* __restrict__ eb5,
    const float* __restrict__ eb6,
    const float* __restrict__ ewo, const float* __restrict__ ebo,
    float* __restrict__ out) {
    int t = blockIdx.x;
    int e, base = 0, n = 0;
    for (e = 0; e < NE; e++) {
        n = g_count[e];
        int T = (n + 63) >> 6;
        if (t < base + T) break;
        base += T;
    }
    if (e == NE) return;
    const int start = (t - base) * 64;
    const int nrows = min(64, n - start);

    extern __shared__ u16 smu[];
    u16* a_hi = smu;                    // 64*264
    u16* a_lo = smu + 16896;
    u16* h_hi = smu + 2 * 16896;        // 64*104
    u16* h_lo = h_hi + 6656;
    u16* wst  = smu + 2 * 16896 + 2 * 6656;
    __shared__ int ridx[64];
    const int tid = threadIdx.x;
    const int lane = tid & 31, wid = tid >> 5;
    const int m0 = (wid & 1) * 32, n_off = (wid >> 1) * 64;

    if (tid < 64) ridx[tid] = (tid < nrows) ? g_list[e][start + tid] : -1;
    __syncthreads();

    // gather h0 = concat(x, latent chunk e) split into fp16 hi/lo planes
    for (int idx = tid; idx < 64 * 104; idx += 256) {
        int r = idx / 104, c = idx - r * 104;
        int gi = ridx[r];
        float v = 0.f;
        if (gi >= 0) {
            if (c < 63)      v = x[gi * 63 + c];
            else if (c < 95) v = sl[gi * 256 + e * CHUNKD + (c - 63)];
        }
        split2h(v, h_hi[idx], h_lo[idx]);
    }
    __syncthreads();

    const u32 a_hi_b = (u32)__cvta_generic_to_shared(a_hi)
                     + (u32)((m0 + (lane & 15)) * 528) + (u32)((lane >> 4) * 16);
    const u32 a_lo_b = (u32)__cvta_generic_to_shared(a_lo)
                     + (u32)((m0 + (lane & 15)) * 528) + (u32)((lane >> 4) * 16);
    const u32 h_hi_b = (u32)__cvta_generic_to_shared(h_hi)
                     + (u32)((m0 + (lane & 15)) * 208) + (u32)((lane >> 4) * 16);
    const u32 h_lo_b = (u32)__cvta_generic_to_shared(h_lo)
                     + (u32)((m0 + (lane & 15)) * 208) + (u32)((lane >> 4) * 16);
    const u32 wstu = (u32)__cvta_generic_to_shared(wst);
    const u32 bboff = (u32)(((lane & 15) * 264 + n_off + (lane >> 4) * 8) * 2);

    const u16* WH = g_wh + (size_t)e * WROWS * 256;
    const u16* WL = g_wl + (size_t)e * WROWS * 256;
    float acc[2][8][4];

    // L0: h0 (K=96) -> 256
    zero_acc_tc(acc);
    gemm_tc3(acc, h_hi_b, h_lo_b, 208, WH, WL, 3, wstu, bboff, tid);
    __syncthreads();
    epi_relu(acc, eb0 + e * 256, a_hi, a_lo, tid);
    __syncthreads();

    // L1..L4: 256 -> 256
    const float* bl4[4] = { eb1, eb2, eb3, eb4 };
#pragma unroll 1
    for (int l = 0; l < 4; l++) {
        zero_acc_tc(acc);
        gemm_tc3(acc, a_hi_b, a_lo_b, 528,
                 WH + (size_t)(96 + l * 256) * 256, WL + (size_t)(96 + l * 256) * 256,
                 8, wstu, bboff, tid);
        __syncthreads();
        epi_relu(acc, bl4[l] + e * 256, a_hi, a_lo, tid);
        __syncthreads();
    }

    // L5 (skip): act part (K=256) + h0 part (K=96)
    zero_acc_tc(acc);
    gemm_tc3(acc, a_hi_b, a_lo_b, 528,
             WH + (size_t)1120 * 256, WL + (size_t)1120 * 256, 8, wstu, bboff, tid);
    gemm_tc3(acc, h_hi_b, h_lo_b, 208,
             WH + (size_t)1376 * 256, WL + (size_t)1376 * 256, 3, wstu, bboff, tid);
    __syncthreads();
    epi_relu(acc, eb5 + e * 256, a_hi, a_lo, tid);
    __syncthreads();

    // L6
    zero_acc_tc(acc);
    gemm_tc3(acc, a_hi_b, a_lo_b, 528,
             WH + (size_t)1472 * 256, WL + (size_t)1472 * 256, 8, wstu, bboff, tid);
    __syncthreads();
    epi_relu(acc, eb6 + e * 256, a_hi, a_lo, tid);
    __syncthreads();

    // output head: y = act @ ewo[e] + ebo[e]; combine with gate
    {
        int r = tid >> 2, o = tid & 3;
        if (r < nrows) {
            float d = ebo[e * 4 + o];
            const float* wo = ewo + (size_t)e * 1024 + o;
            const __half2* ah2 = (const __half2*)(a_hi + r * 264);
            const __half2* al2 = (const __half2*)(a_lo + r * 264);
#pragma unroll 8
            for (int k = 0; k < 128; k++) {
                float2 hv = __half22float2(ah2[k]);
                float2 lv = __half22float2(al2[k]);
                d += (hv.x + lv.x) * wo[(2 * k) * 4];
                d += (hv.y + lv.y) * wo[(2 * k + 1) * 4];
            }
            int gi = ridx[r];
            float comb = g_gv[gi] * expf(d);
            if (comb == 0.f) comb = EPSF;
            out[gi * 4 + o] = logf(comb);
        }
    }
}

// ---------------- launch -----------------------------------------------------
extern "C" void kernel_launch(void* const* d_in, const int* in_sizes, int n_in,
                              void* d_out, int out_size) {
    const float* x   = (const float*)d_in[0];
    const float* sl  = (const float*)d_in[1];
    const float* gw1 = (const float*)d_in[2];
    const float* gb1 = (const float*)d_in[3];
    const float* gw2 = (const float*)d_in[4];
    const float* gb2 = (const float*)d_in[5];
    const float* lng = (const float*)d_in[6];
    const float* lnb = (const float*)d_in[7];
    const float* gw3 = (const float*)d_in[8];
    const float* gb3 = (const float*)d_in[9];
    const float* ew0 = (const float*)d_in[10];
    const float* eb0 = (const float*)d_in[11];
    const float* ew1 = (const float*)d_in[12];
    const float* eb1 = (const float*)d_in[13];
    const float* ew2 = (const float*)d_in[14];
    const float* eb2 = (const float*)d_in[15];
    const float* ew3 = (const float*)d_in[16];
    const float* eb3 = (const float*)d_in[17];
    const float* ew4 = (const float*)d_in[18];
    const float* eb4 = (const float*)d_in[19];
    const float* ew5 = (const float*)d_in[20];
    const float* eb5 = (const float*)d_in[21];
    const float* ew6 = (const float*)d_in[22];
    const float* eb6 = (const float*)d_in[23];
    const float* ewo = (const float*)d_in[24];
    const float* ebo = (const float*)d_in[25];
    float* out = (float*)d_out;

    cudaFuncSetAttribute(gate_kernel, cudaFuncAttributeMaxDynamicSharedMemorySize,
                         GATE_SMEM_B);
    cudaFuncSetAttribute(expert_kernel, cudaFuncAttributeMaxDynamicSharedMemorySize,
                         EXP_SMEM_B);

    reset_kernel<<<1, 32>>>();
    convert_weights<<<NE * WROWS, 256>>>(ew0, ew1, ew2, ew3, ew4, ew5, ew6);
    convert_gate_weights<<<GWROWS, 256>>>(gw1, gw2);
    gate_kernel<<<BPTS / 64, 256, GATE_SMEM_B>>>(x, sl, gb1, gb2,
                                                 lng, lnb, gw3, gb3);
    expert_kernel<<<EXP_TILES, 256, EXP_SMEM_B>>>(
        x, sl, eb0, eb1, eb2, eb3, eb4, eb5, eb6, ewo, ebo, out);
}

// round 8
// speedup vs baseline: 2.0380x; 1.1702x over previous
#include <cuda_runtime.h>
#include <cuda_fp16.h>

#define BPTS   16384
#define NE     8
#define CHUNKD 32
#define EPSF   2.220446049250313e-16f
#define WROWS  1728           // padded expert K rows: 96+4*256+256+96+256
#define GWROWS 576            // gate: 320 (gw1 padded) + 256 (gw2)
#define NT     512
typedef unsigned int u32;
typedef unsigned short u16;

// ---------------- scratch (static device globals) ----------------------------
__device__ int   g_count[NE];
__device__ int   g_list[NE][BPTS];
__device__ float g_gv[BPTS];
// expert weights row-major [e][k][n(256)] fp16 hi / lo
__device__ u16 g_wh[NE * WROWS * 256];
__device__ u16 g_wl[NE * WROWS * 256];
// gate weights [k(576)][n(256)] fp16 hi / lo
__device__ u16 g_gh[GWROWS * 256];
__device__ u16 g_gl[GWROWS * 256];

// ---------------- tensor-core helpers ----------------------------------------
__device__ __forceinline__ void mma_f16(float d[4], u32 a0, u32 a1, u32 a2, u32 a3,
                                        u32 b0, u32 b1) {
    asm volatile(
        "mma.sync.aligned.m16n8k16.row.col.f32.f16.f16.f32 "
        "{%0,%1,%2,%3}, {%4,%5,%6,%7}, {%8,%9}, {%0,%1,%2,%3};"
        : "+f"(d[0]), "+f"(d[1]), "+f"(d[2]), "+f"(d[3])
        : "r"(a0), "r"(a1), "r"(a2), "r"(a3), "r"(b0), "r"(b1));
}
__device__ __forceinline__ void ldsm4(u32 r[4], u32 addr) {
    asm volatile("ldmatrix.sync.aligned.m8n8.x4.shared.b16 {%0,%1,%2,%3}, [%4];"
                 : "=r"(r[0]), "=r"(r[1]), "=r"(r[2]), "=r"(r[3]) : "r"(addr));
}
__device__ __forceinline__ void ldsm4t(u32 r[4], u32 addr) {
    asm volatile("ldmatrix.sync.aligned.m8n8.x4.trans.shared.b16 {%0,%1,%2,%3}, [%4];"
                 : "=r"(r[0]), "=r"(r[1]), "=r"(r[2]), "=r"(r[3]) : "r"(addr));
}
#define CP16(dst, src) \
    asm volatile("cp.async.cg.shared.global [%0], [%1], 16;" :: "r"(dst), "l"(src))
#define CPCOMMIT() asm volatile("cp.async.commit_group;")
#define CPWAIT0()  asm volatile("cp.async.wait_group 0;")

__device__ __forceinline__ void split2h(float v, u16& h, u16& l) {
    __half hh = __float2half_rn(v);
    __half ll = __float2half_rn(v - __half2float(hh));
    h = *(u16*)&hh;  l = *(u16*)&ll;
}

// ---------------- weight chunk staging (32 k-rows, hi+lo) ---------------------
// smem plane rows stride 264 u16 (528 B); hi plane then lo plane (+16896 B).
// One buffer = 33792 B. 2048 x 16B copies -> 4 per thread (512 threads).
__device__ __forceinline__ void stage_chunk32(
    u32 dst_base, const u16* __restrict__ Wh, const u16* __restrict__ Wl,
    int c, int tid) {
#pragma unroll
    for (int p = 0; p < 4; p++) {
        int uu = tid + p * NT;
        int isLo = uu >> 10;
        int v = uu & 1023;
        int row = v >> 5, col = v & 31;
        const u16* src = (isLo ? Wl : Wh) + (size_t)(c * 32 + row) * 256 + col * 8;
        u32 dst = dst_base + isLo * 16896 + row * 528 + col * 16;
        CP16(dst, src);
    }
}

// GEMM: acc[64x256] += A[64xK] @ W[Kx256]; A pre-split fp16 hi/lo planes in
// smem (ldmatrix), W staged hi/lo via cp.async double-buffered 32-row chunks.
// 16 warps: warp grid 2(M=32) x 8(N=32); acc[2][4][4] per thread.
__device__ __forceinline__ void gemm_tc3(
    float (&acc)[2][4][4],
    u32 a_hi_b, u32 a_lo_b, int rowbytes,
    const u16* __restrict__ Wh, const u16* __restrict__ Wl,
    int nc, u32 wstu, u32 bboff, int tid)
{
    stage_chunk32(wstu, Wh, Wl, 0, tid);
    CPCOMMIT();
    u32 ah[2][4], al[2][4], bh[4], bl[4];
    for (int c = 0; c < nc; c++) {
        CPWAIT0();
        __syncthreads();
        if (c + 1 < nc) {
            stage_chunk32(wstu + ((c + 1) & 1) * 33792, Wh, Wl, c + 1, tid);
            CPCOMMIT();
        }
        const u32 cur = wstu + (c & 1) * 33792;
#pragma unroll
        for (int ks = 0; ks < 2; ks++) {
            const u32 aoff = (u32)(c * 64 + ks * 32);
            ldsm4(ah[0], a_hi_b + aoff);
            ldsm4(ah[1], a_hi_b + 16 * rowbytes + aoff);
            ldsm4(al[0], a_lo_b + aoff);
            ldsm4(al[1], a_lo_b + 16 * rowbytes + aoff);
            const u32 bb = cur + bboff + ks * 8448;
#pragma unroll
            for (int gg = 0; gg < 2; gg++) {
                ldsm4t(bh, bb + gg * 32);
                ldsm4t(bl, bb + 16896 + gg * 32);
#pragma unroll
                for (int nb = 0; nb < 2; nb++) {
                    const int j = gg * 2 + nb;
                    const u32 b0 = bh[2 * nb], b1 = bh[2 * nb + 1];
                    const u32 c0 = bl[2 * nb], c1 = bl[2 * nb + 1];
#pragma unroll
                    for (int im = 0; im < 2; im++) {
                        mma_f16(acc[im][j], ah[im][0], ah[im][1], ah[im][2], ah[im][3], b0, b1);
                        mma_f16(acc[im][j], al[im][0], al[im][1], al[im][2], al[im][3], b0, b1);
                        mma_f16(acc[im][j], ah[im][0], ah[im][1], ah[im][2], ah[im][3], c0, c1);
                    }
                }
            }
        }
    }
}

__device__ __forceinline__ void zero_acc_tc(float (&acc)[2][4][4]) {
#pragma unroll
    for (int im = 0; im < 2; im++)
#pragma unroll
        for (int j = 0; j < 4; j++)
#pragma unroll
            for (int q = 0; q < 4; q++) acc[im][j][q] = 0.f;
}

// epilogue: relu(acc+bias) -> split fp16 hi/lo planes (stride 264)
__device__ __forceinline__ void epi_relu(const float (&acc)[2][4][4],
                                         const float* __restrict__ bias,
                                         u16* a_hi, u16* a_lo, int tid) {
    const int lane = tid & 31, wid = tid >> 5;
    const int m0 = (wid & 1) * 32, n_off = (wid >> 1) * 32;
    const int g = lane >> 2, tt = lane & 3;
#pragma unroll
    for (int im = 0; im < 2; im++)
#pragma unroll
        for (int j = 0; j < 4; j++) {
            const int c = n_off + j * 8 + 2 * tt;
            const float b0 = bias[c], b1 = bias[c + 1];
            const int rlo = m0 + im * 16 + g, rhi = rlo + 8;
            float v0 = fmaxf(acc[im][j][0] + b0, 0.f);
            float v1 = fmaxf(acc[im][j][1] + b1, 0.f);
            float v2 = fmaxf(acc[im][j][2] + b0, 0.f);
            float v3 = fmaxf(acc[im][j][3] + b1, 0.f);
            __half2 h01 = __floats2half2_rn(v0, v1);
            __half2 h23 = __floats2half2_rn(v2, v3);
            float2 hf01 = __half22float2(h01);
            float2 hf23 = __half22float2(h23);
            __half2 l01 = __floats2half2_rn(v0 - hf01.x, v1 - hf01.y);
            __half2 l23 = __floats2half2_rn(v2 - hf23.x, v3 - hf23.y);
            *(u32*)(a_hi + rlo * 264 + c) = *(u32*)&h01;
            *(u32*)(a_hi + rhi * 264 + c) = *(u32*)&h23;
            *(u32*)(a_lo + rlo * 264 + c) = *(u32*)&l01;
            *(u32*)(a_lo + rhi * 264 + c) = *(u32*)&l23;
        }
}

// gate GEMM2 epilogue: h2 = acc + bias (fp32, stride 257, no relu)
__device__ __forceinline__ void epi_h2(const float (&acc)[2][4][4],
                                       const float* __restrict__ bias,
                                       float* h2, int tid) {
    const int lane = tid & 31, wid = tid >> 5;
    const int m0 = (wid & 1) * 32, n_off = (wid >> 1) * 32;
    const int g = lane >> 2, tt = lane & 3;
#pragma unroll
    for (int im = 0; im < 2; im++)
#pragma unroll
        for (int j = 0; j < 4; j++) {
            const int c = n_off + j * 8 + 2 * tt;
            const float b0 = bias[c], b1 = bias[c + 1];
            const int rlo = m0 + im * 16 + g, rhi = rlo + 8;
            h2[rlo * 257 + c]     = acc[im][j][0] + b0;
            h2[rlo * 257 + c + 1] = acc[im][j][1] + b1;
            h2[rhi * 257 + c]     = acc[im][j][2] + b0;
            h2[rhi * 257 + c + 1] = acc[im][j][3] + b1;
        }
}

// ---------------- kernel 0: reset ---------------------------------------------
__global__ void reset_kernel() {
    if (threadIdx.x < NE) g_count[threadIdx.x] = 0;
}

// ---------------- kernel 0b: split expert weights to fp16 hi/lo ----------------
__global__ void convert_weights(
    const float* __restrict__ ew0, const float* __restrict__ ew1,
    const float* __restrict__ ew2, const float* __restrict__ ew3,
    const float* __restrict__ ew4, const float* __restrict__ ew5,
    const float* __restrict__ ew6) {
    int idx = blockIdx.x * 256 + threadIdx.x;          // < NE*WROWS*256
    int e   = idx / (WROWS * 256);
    int rem = idx - e * (WROWS * 256);
    int r = rem >> 8, n = rem & 255;
    float w = 0.f;
    if (r < 96)        { int k = r;            if (k < 95) w = ew0[((size_t)e * 95 + k) * 256 + n]; }
    else if (r < 352)  { int k = r - 96;       w = ew1[((size_t)e * 256 + k) * 256 + n]; }
    else if (r < 608)  { int k = r - 352;      w = ew2[((size_t)e * 256 + k) * 256 + n]; }
    else if (r < 864)  { int k = r - 608;      w = ew3[((size_t)e * 256 + k) * 256 + n]; }
    else if (r < 1120) { int k = r - 864;      w = ew4[((size_t)e * 256 + k) * 256 + n]; }
    else if (r < 1376) { int k = r - 1120;     w = ew5[((size_t)e * 351 + k) * 256 + n]; }
    else if (r < 1472) { int k = 256 + (r - 1376); if (k < 351) w = ew5[((size_t)e * 351 + k) * 256 + n]; }
    else               { int k = r - 1472;     w = ew6[((size_t)e * 256 + k) * 256 + n]; }
    split2h(w, g_wh[idx], g_wl[idx]);
}

// ---------------- kernel 0c: split gate weights --------------------------------
__global__ void convert_gate_weights(const float* __restrict__ gw1,
                                     const float* __restrict__ gw2) {
    int idx = blockIdx.x * 256 + threadIdx.x;          // < GWROWS*256
    int r = idx >> 8, n = idx & 255;
    float w = 0.f;
    if (r < 320) { if (r < 319) w = gw1[(size_t)r * 256 + n]; }
    else         w = gw2[(size_t)(r - 320) * 256 + n];
    split2h(w, g_gh[idx], g_gl[idx]);
}

// ---------------- kernel 1: gate network + routing (TC fp16-split) -------------
// smem bytes: region0 [0, 84992): gi planes (2 x 64x328 u16) -> h1 planes
//             (2 x 64x264 u16) -> h2 fp32 (64x257) + logits (at 66048)
//             wst at 84992: 2 x 33792 B
#define GATE_SMEM_B (84992 + 67584)

__global__ __launch_bounds__(NT, 1) void gate_kernel(
    const float* __restrict__ x,  const float* __restrict__ sl,
    const float* __restrict__ gb1, const float* __restrict__ gb2,
    const float* __restrict__ lng, const float* __restrict__ lnb,
    const float* __restrict__ gw3, const float* __restrict__ gb3) {
    extern __shared__ u16 smu[];
    u16* gi_hi = smu;                       // 64*328
    u16* gi_lo = smu + 20992;
    u16* a_hi  = smu;                       // 64*264 (after GEMM1)
    u16* a_lo  = smu + 16896;
    float* h2    = (float*)smu;             // 64*257 (after GEMM2)
    float* lgbuf = (float*)((char*)smu + 66048);   // 64*8
    const u32 wstu = (u32)__cvta_generic_to_shared((char*)smu + 84992);

    const int tid = threadIdx.x;
    const int row0 = blockIdx.x * 64;
    const int lane = tid & 31, wid = tid >> 5;
    const int m0 = (wid & 1) * 32, n_off = (wid >> 1) * 32;
    const u32 bboff = (u32)(((lane & 15) * 264 + n_off + (lane >> 4) * 8) * 2);

    // gather g_in = concat(x, shape_latent) split into fp16 hi/lo (stride 328)
    for (int idx = tid; idx < 64 * 328; idx += NT) {
        int r = idx / 328, c = idx - r * 328;
        int gi = row0 + r;
        float v = 0.f;
        if (c < 63)       v = x[gi * 63 + c];
        else if (c < 319) v = sl[gi * 256 + (c - 63)];
        split2h(v, gi_hi[idx], gi_lo[idx]);
    }
    __syncthreads();

    const u32 gihi_b = (u32)__cvta_generic_to_shared(gi_hi)
                     + (u32)((m0 + (lane & 15)) * 656) + (u32)((lane >> 4) * 16);
    const u32 gilo_b = (u32)__cvta_generic_to_shared(gi_lo)
                     + (u32)((m0 + (lane & 15)) * 656) + (u32)((lane >> 4) * 16);
    const u32 ahi_b = (u32)__cvta_generic_to_shared(a_hi)
                    + (u32)((m0 + (lane & 15)) * 528) + (u32)((lane >> 4) * 16);
    const u32 alo_b = (u32)__cvta_generic_to_shared(a_lo)
                    + (u32)((m0 + (lane & 15)) * 528) + (u32)((lane >> 4) * 16);

    float acc[2][4][4];

    // GEMM1: g_in (K=320) @ gw1 -> relu -> h1 split planes
    zero_acc_tc(acc);
    gemm_tc3(acc, gihi_b, gilo_b, 656, g_gh, g_gl, 10, wstu, bboff, tid);
    __syncthreads();
    epi_relu(acc, gb1, a_hi, a_lo, tid);
    __syncthreads();

    // GEMM2: h1 (K=256) @ gw2 -> h2 fp32
    zero_acc_tc(acc);
    gemm_tc3(acc, ahi_b, alo_b, 528, g_gh + 320 * 256, g_gl + 320 * 256,
             8, wstu, bboff, tid);
    __syncthreads();
    epi_h2(acc, gb2, h2, tid);
    __syncthreads();

    // LayerNorm per row: 8 threads/row, two-pass
    {
        int r = tid >> 3, sub = tid & 7;
        float* h2r = h2 + r * 257;
        float s = 0.f;
#pragma unroll 8
        for (int k = 0; k < 32; k++) s += h2r[sub + 8 * k];
        s += __shfl_xor_sync(0xffffffffu, s, 1);
        s += __shfl_xor_sync(0xffffffffu, s, 2);
        s += __shfl_xor_sync(0xffffffffu, s, 4);
        float mu = s * (1.f / 256.f);
        float vv = 0.f;
#pragma unroll 8
        for (int k = 0; k < 32; k++) {
            float d = h2r[sub + 8 * k] - mu;
            vv += d * d;
        }
        vv += __shfl_xor_sync(0xffffffffu, vv, 1);
        vv += __shfl_xor_sync(0xffffffffu, vv, 2);
        vv += __shfl_xor_sync(0xffffffffu, vv, 4);
        float rstd = rsqrtf(vv * (1.f / 256.f) + 1e-5f);
#pragma unroll 8
        for (int k = 0; k < 32; k++) {
            int c = sub + 8 * k;
            float nv = (h2r[c] - mu) * rstd;
            h2r[c] = nv * lng[c] + lnb[c];
        }
    }
    __syncthreads();

    // logits = h2 @ gw3 + gb3 (fp32 scalar; one task per thread)
    {
        int r = tid >> 3, e = tid & 7;
        float d = gb3[e];
        const float* h2r = h2 + r * 257;
#pragma unroll 8
        for (int k = 0; k < 256; k++) d += h2r[k] * gw3[k * 8 + e];
        lgbuf[r * 8 + e] = d;
    }
    __syncthreads();

    // softmax / argmax / append to expert list
    if (tid < 64) {
        int gi = row0 + tid;
        const float* lg = lgbuf + tid * 8;
        float best = lg[0];
        int bi = 0;
#pragma unroll
        for (int e = 1; e < 8; e++) {
            float v = lg[e];
            if (v > best) { best = v; bi = e; }
        }
        float ssum = 0.f;
#pragma unroll
        for (int e = 0; e < 8; e++) ssum += expf(lg[e] - best);
        g_gv[gi] = 1.f / ssum;
        int pos = atomicAdd(&g_count[bi], 1);
        g_list[bi][pos] = gi;
    }
}

// ---------------- kernel 2: routed expert MLP (TC, cp.async staged) -----------
// smem elems (u16): a_hi[16896] a_lo[16896] h_hi[6656] h_lo[6656] wst[33792]
#define EXP_SMEM_B ((16896 * 2 + 6656 * 2 + 33792) * 2)
#define EXP_TILES  (BPTS / 64 + NE)

__global__ __launch_bounds__(NT, 1) void expert_kernel(
    const float* __restrict__ x,  const float* __restrict__ sl,
    const float* __restrict__ eb0, const float* __restrict__ eb1,
    const float* __restrict__ eb2, const float* __restrict__ eb3,
    const float* __restrict__ eb4, const float* __restrict__ eb5,
    const float* __restrict__ eb6,
    const float* __restrict__ ewo, const float* __restrict__ ebo,
    float* __restrict__ out) {
    int t = blockIdx.x;
    int e, base = 0, n = 0;
    for (e = 0; e < NE; e++) {
        n = g_count[e];
        int T = (n + 63) >> 6;
        if (t < base + T) break;
        base += T;
    }
    if (e == NE) return;
    const int start = (t - base) * 64;
    const int nrows = min(64, n - start);

    extern __shared__ u16 smu[];
    u16* a_hi = smu;                    // 64*264
    u16* a_lo = smu + 16896;
    u16* h_hi = smu + 2 * 16896;        // 64*104
    u16* h_lo = h_hi + 6656;
    u16* wst  = smu + 2 * 16896 + 2 * 6656;
    __shared__ int ridx[64];
    const int tid = threadIdx.x;
    const int lane = tid & 31, wid = tid >> 5;
    const int m0 = (wid & 1) * 32, n_off = (wid >> 1) * 32;

    if (tid < 64) ridx[tid] = (tid < nrows) ? g_list[e][start + tid] : -1;
    __syncthreads();

    // gather h0 = concat(x, latent chunk e) split into fp16 hi/lo planes
    for (int idx = tid; idx < 64 * 104; idx += NT) {
        int r = idx / 104, c = idx - r * 104;
        int gi = ridx[r];
        float v = 0.f;
        if (gi >= 0) {
            if (c < 63)      v = x[gi * 63 + c];
            else if (c < 95) v = sl[gi * 256 + e * CHUNKD + (c - 63)];
        }
        split2h(v, h_hi[idx], h_lo[idx]);
    }
    __syncthreads();

    const u32 a_hi_b = (u32)__cvta_generic_to_shared(a_hi)
                     + (u32)((m0 + (lane & 15)) * 528) + (u32)((lane >> 4) * 16);
    const u32 a_lo_b = (u32)__cvta_generic_to_shared(a_lo)
                     + (u32)((m0 + (lane & 15)) * 528) + (u32)((lane >> 4) * 16);
    const u32 h_hi_b = (u32)__cvta_generic_to_shared(h_hi)
                     + (u32)((m0 + (lane & 15)) * 208) + (u32)((lane >> 4) * 16);
    const u32 h_lo_b = (u32)__cvta_generic_to_shared(h_lo)
                     + (u32)((m0 + (lane & 15)) * 208) + (u32)((lane >> 4) * 16);
    const u32 wstu = (u32)__cvta_generic_to_shared(wst);
    const u32 bboff = (u32)(((lane & 15) * 264 + n_off + (lane >> 4) * 8) * 2);

    const u16* WH = g_wh + (size_t)e * WROWS * 256;
    const u16* WL = g_wl + (size_t)e * WROWS * 256;
    float acc[2][4][4];

    // L0: h0 (K=96) -> 256
    zero_acc_tc(acc);
    gemm_tc3(acc, h_hi_b, h_lo_b, 208, WH, WL, 3, wstu, bboff, tid);
    __syncthreads();
    epi_relu(acc, eb0 + e * 256, a_hi, a_lo, tid);
    __syncthreads();

    // L1..L4: 256 -> 256
    const float* bl4[4] = { eb1, eb2, eb3, eb4 };
#pragma unroll 1
    for (int l = 0; l < 4; l++) {
        zero_acc_tc(acc);
        gemm_tc3(acc, a_hi_b, a_lo_b, 528,
                 WH + (size_t)(96 + l * 256) * 256, WL + (size_t)(96 + l * 256) * 256,
                 8, wstu, bboff, tid);
        __syncthreads();
        epi_relu(acc, bl4[l] + e * 256, a_hi, a_lo, tid);
        __syncthreads();
    }

    // L5 (skip): act part (K=256) + h0 part (K=96)
    zero_acc_tc(acc);
    gemm_tc3(acc, a_hi_b, a_lo_b, 528,
             WH + (size_t)1120 * 256, WL + (size_t)1120 * 256, 8, wstu, bboff, tid);
    gemm_tc3(acc, h_hi_b, h_lo_b, 208,
             WH + (size_t)1376 * 256, WL + (size_t)1376 * 256, 3, wstu, bboff, tid);
    __syncthreads();
    epi_relu(acc, eb5 + e * 256, a_hi, a_lo, tid);
    __syncthreads();

    // L6
    zero_acc_tc(acc);
    gemm_tc3(acc, a_hi_b, a_lo_b, 528,
             WH + (size_t)1472 * 256, WL + (size_t)1472 * 256, 8, wstu, bboff, tid);
    __syncthreads();
    epi_relu(acc, eb6 + e * 256, a_hi, a_lo, tid);
    __syncthreads();

    // output head: y = act @ ewo[e] + ebo[e]; combine with gate
    if (tid < 256) {
        int r = tid >> 2, o = tid & 3;
        if (r < nrows) {
            float d = ebo[e * 4 + o];
            const float* wo = ewo + (size_t)e * 1024 + o;
            const __half2* ah2 = (const __half2*)(a_hi + r * 264);
            const __half2* al2 = (const __half2*)(a_lo + r * 264);
#pragma unroll 8
            for (int k = 0; k < 128; k++) {
                float2 hv = __half22float2(ah2[k]);
                float2 lv = __half22float2(al2[k]);
                d += (hv.x + lv.x) * wo[(2 * k) * 4];
                d += (hv.y + lv.y) * wo[(2 * k + 1) * 4];
            }
            int gi = ridx[r];
            float comb = g_gv[gi] * expf(d);
            if (comb == 0.f) comb = EPSF;
            out[gi * 4 + o] = logf(comb);
        }
    }
}

// ---------------- launch -----------------------------------------------------
extern "C" void kernel_launch(void* const* d_in, const int* in_sizes, int n_in,
                              void* d_out, int out_size) {
    const float* x   = (const float*)d_in[0];
    const float* sl  = (const float*)d_in[1];
    const float* gw1 = (const float*)d_in[2];
    const float* gb1 = (const float*)d_in[3];
    const float* gw2 = (const float*)d_in[4];
    const float* gb2 = (const float*)d_in[5];
    const float* lng = (const float*)d_in[6];
    const float* lnb = (const float*)d_in[7];
    const float* gw3 = (const float*)d_in[8];
    const float* gb3 = (const float*)d_in[9];
    const float* ew0 = (const float*)d_in[10];
    const float* eb0 = (const float*)d_in[11];
    const float* ew1 = (const float*)d_in[12];
    const float* eb1 = (const float*)d_in[13];
    const float* ew2 = (const float*)d_in[14];
    const float* eb2 = (const float*)d_in[15];
    const float* ew3 = (const float*)d_in[16];
    const float* eb3 = (const float*)d_in[17];
    const float* ew4 = (const float*)d_in[18];
    const float* eb4 = (const float*)d_in[19];
    const float* ew5 = (const float*)d_in[20];
    const float* eb5 = (const float*)d_in[21];
    const float* ew6 = (const float*)d_in[22];
    const float* eb6 = (const float*)d_in[23];
    const float* ewo = (const float*)d_in[24];
    const float* ebo = (const float*)d_in[25];
    float* out = (float*)d_out;

    cudaFuncSetAttribute(gate_kernel, cudaFuncAttributeMaxDynamicSharedMemorySize,
                         GATE_SMEM_B);
    cudaFuncSetAttribute(expert_kernel, cudaFuncAttributeMaxDynamicSharedMemorySize,
                         EXP_SMEM_B);

    reset_kernel<<<1, 32>>>();
    convert_weights<<<NE * WROWS, 256>>>(ew0, ew1, ew2, ew3, ew4, ew5, ew6);
    convert_gate_weights<<<GWROWS, 256>>>(gw1, gw2);
    gate_kernel<<<BPTS / 64, NT, GATE_SMEM_B>>>(x, sl, gb1, gb2,
                                                lng, lnb, gw3, gb3);
    expert_kernel<<<EXP_TILES, NT, EXP_SMEM_B>>>(
        x, sl, eb0, eb1, eb2, eb3, eb4, eb5, eb6, ewo, ebo, out);
}